// round 12
// baseline (speedup 1.0000x reference)
#include <cuda_runtime.h>
#include <cstdint>

#define D_MODEL 1024
#define HEADS   16
#define DK      64
#define BATCH   2
#define SEQ     2048
#define MTOK    (BATCH * SEQ)   // 4096
#define NEGV    -1e9f

#define NW_ELEM (D_MODEL * D_MODEL)

// Scratch (allocation-free: static device globals)
__device__ float g_q[(size_t)MTOK * D_MODEL];
__device__ float g_k[(size_t)MTOK * D_MODEL];
__device__ float g_v[(size_t)MTOK * D_MODEL];
__device__ float g_ctx[(size_t)MTOK * D_MODEL];
__device__ float g_xr[(size_t)MTOK * D_MODEL];   // tf32-rounded x
__device__ float g_wr[(size_t)4 * NW_ELEM];      // tf32-rounded wq|wk|wv|wo

// ---------------------------------------------------------------------------
__device__ __forceinline__ unsigned f2tf(float x) {
    unsigned r;
    asm("cvt.rna.tf32.f32 %0, %1;" : "=r"(r) : "f"(x));
    return r;
}
__device__ __forceinline__ float f2tf_f(float x) { return __uint_as_float(f2tf(x)); }

// Slot convention (both A and B sides, consistently): k-slot tg holds feature
// k0+2tg, k-slot tg+4 holds feature k0+2tg+1. The mma dot-product is
// order-agnostic over k, so this is exact — and it makes every fragment pair
// an adjacent float2 (one LDS.64 instead of two LDS.32).
__device__ __forceinline__ void mma8(float* c, const unsigned* a, unsigned b0, unsigned b1) {
    asm volatile(
        "mma.sync.aligned.m16n8k8.row.col.f32.tf32.tf32.f32 "
        "{%0,%1,%2,%3},{%4,%5,%6,%7},{%8,%9},{%0,%1,%2,%3};"
        : "+f"(c[0]), "+f"(c[1]), "+f"(c[2]), "+f"(c[3])
        : "r"(a[0]), "r"(a[1]), "r"(a[2]), "r"(a[3]), "r"(b0), "r"(b1));
}

__device__ __forceinline__ void cp16(uint32_t dst, const void* src) {
    asm volatile("cp.async.cg.shared.global [%0], [%1], 16;" :: "r"(dst), "l"(src));
}
__device__ __forceinline__ void cp_commit() {
    asm volatile("cp.async.commit_group;");
}
template <int N> __device__ __forceinline__ void cp_wait() {
    asm volatile("cp.async.wait_group %0;" :: "n"(N));
}

// ---------------------------------------------------------------------------
// Pre-round x and the four weights to tf32 (rna).
// ---------------------------------------------------------------------------
__global__ void round_all(const float* __restrict__ x,  const float* __restrict__ wq,
                          const float* __restrict__ wk, const float* __restrict__ wv,
                          const float* __restrict__ wo, float* __restrict__ xr,
                          float* __restrict__ wr) {
    const int NX = MTOK * D_MODEL / 4;
    const int NWq = NW_ELEM / 4;
    int i = blockIdx.x * blockDim.x + threadIdx.x;
    const float4* src;
    float4* dst;
    int off;
    if (i < NX) {
        src = (const float4*)x; dst = (float4*)xr; off = i;
    } else {
        int j = i - NX;
        int w = j >> 18;
        off = j & (NWq - 1);
        src = (const float4*)(w == 0 ? wq : w == 1 ? wk : w == 2 ? wv : wo);
        dst = (float4*)(wr + (size_t)w * NW_ELEM);
    }
    float4 t = src[off];
    dst[off] = make_float4(f2tf_f(t.x), f2tf_f(t.y), f2tf_f(t.z), f2tf_f(t.w));
}

// ---------------------------------------------------------------------------
// tf32 GEMM mainloop (NT): 128x128 tile, BK=32, cp.async double-buffered,
// 256 thr = 8 warps (2m x 4n). Pitch 40 (== 8 mod 32): LDS.64 fragment loads
// are bank-conflict-free ({8g+2tg} distinct per half-warp phase).
// ---------------------------------------------------------------------------
#define BK    32
#define GROW  40
#define STAGE (128 * GROW)
#define GEMM_SMEM (4 * STAGE * 4)   // 81920 B

__device__ __forceinline__ void gemm_main(const float* __restrict__ A,
                                          const float* __restrict__ B,
                                          float cf[4][4][4]) {
    extern __shared__ float sh[];
    float* As = sh;
    float* Bs = sh + 2 * STAGE;

    const int tid  = threadIdx.x;
    const int lane = tid & 31;
    const int wid  = tid >> 5;
    const int g    = lane >> 2;
    const int tg   = lane & 3;
    const int wm   = wid & 1;
    const int wn   = wid >> 1;
    const int bm   = blockIdx.y * 128;
    const int bn   = blockIdx.x * 128;

    const int r0 = tid >> 3;
    const int kc = tid & 7;
    const uint32_t sA = (uint32_t)__cvta_generic_to_shared(As) + (r0 * GROW + kc * 4) * 4;
    const uint32_t sB = (uint32_t)__cvta_generic_to_shared(Bs) + (r0 * GROW + kc * 4) * 4;
    const float* Ag = A + (size_t)(bm + r0) * D_MODEL + kc * 4;
    const float* Bg = B + (size_t)(bn + r0) * D_MODEL + kc * 4;

#pragma unroll
    for (int mt = 0; mt < 4; mt++)
#pragma unroll
        for (int nt = 0; nt < 4; nt++)
#pragma unroll
            for (int j = 0; j < 4; j++) cf[mt][nt][j] = 0.f;

    const int NIT = D_MODEL / BK;

#pragma unroll
    for (int i = 0; i < 4; i++) {
        cp16(sA + i * 32 * GROW * 4, Ag + (size_t)i * 32 * D_MODEL);
        cp16(sB + i * 32 * GROW * 4, Bg + (size_t)i * 32 * D_MODEL);
    }
    cp_commit();

#pragma unroll 1
    for (int it = 0; it < NIT; it++) {
        if (it + 1 < NIT) {
            int s = (it + 1) & 1;
            int k0 = (it + 1) * BK;
            uint32_t dA = sA + s * STAGE * 4;
            uint32_t dB = sB + s * STAGE * 4;
#pragma unroll
            for (int i = 0; i < 4; i++) {
                cp16(dA + i * 32 * GROW * 4, Ag + k0 + (size_t)i * 32 * D_MODEL);
                cp16(dB + i * 32 * GROW * 4, Bg + k0 + (size_t)i * 32 * D_MODEL);
            }
            cp_commit();
            cp_wait<1>();
        } else {
            cp_wait<0>();
        }
        __syncthreads();

        const float* as = As + (it & 1) * STAGE;
        const float* bs = Bs + (it & 1) * STAGE;
#pragma unroll
        for (int kb = 0; kb < BK; kb += 8) {
            unsigned af[4][4];
#pragma unroll
            for (int mt = 0; mt < 4; mt++) {
                int m = wm * 64 + mt * 16 + g;
                float2 ta = *(const float2*)&as[m * GROW + kb + 2 * tg];
                float2 tb = *(const float2*)&as[(m + 8) * GROW + kb + 2 * tg];
                af[mt][0] = __float_as_uint(ta.x);   // slot tg   <- feature kb+2tg
                af[mt][1] = __float_as_uint(tb.x);
                af[mt][2] = __float_as_uint(ta.y);   // slot tg+4 <- feature kb+2tg+1
                af[mt][3] = __float_as_uint(tb.y);
            }
#pragma unroll
            for (int nt = 0; nt < 4; nt++) {
                int n = wn * 32 + nt * 8 + g;
                float2 tn = *(const float2*)&bs[n * GROW + kb + 2 * tg];
                unsigned bb0 = __float_as_uint(tn.x);
                unsigned bb1 = __float_as_uint(tn.y);
#pragma unroll
                for (int mt = 0; mt < 4; mt++) mma8(cf[mt][nt], af[mt], bb0, bb1);
            }
        }
        __syncthreads();
    }
}

// Plain output GEMM (final projection) — writes d_out directly.
__global__ __launch_bounds__(256, 2) void gemm_out(const float* __restrict__ A,
                                                   const float* __restrict__ B,
                                                   float* __restrict__ C) {
    float cf[4][4][4];
    gemm_main(A, B, cf);

    const int lane = threadIdx.x & 31;
    const int wid  = threadIdx.x >> 5;
    const int g    = lane >> 2;
    const int tg   = lane & 3;
    const int wm   = wid & 1;
    const int wn   = wid >> 1;
    const int bm   = blockIdx.y * 128;
    const int bn   = blockIdx.x * 128;

#pragma unroll
    for (int mt = 0; mt < 4; mt++) {
        int m0 = bm + wm * 64 + mt * 16 + g;
#pragma unroll
        for (int nt = 0; nt < 4; nt++) {
            int n0 = bn + wn * 32 + nt * 8 + 2 * tg;
            *(float2*)&C[(size_t)m0 * D_MODEL + n0] =
                make_float2(cf[mt][nt][0], cf[mt][nt][1]);
            *(float2*)&C[(size_t)(m0 + 8) * D_MODEL + n0] =
                make_float2(cf[mt][nt][2], cf[mt][nt][3]);
        }
    }
}

// QKV GEMM with fused RoPE + tf32 rounding epilogue.
__global__ __launch_bounds__(256, 2) void gemm_qkv(const float* __restrict__ x,
                                                   const float* __restrict__ w,
                                                   float* __restrict__ q,
                                                   float* __restrict__ k,
                                                   float* __restrict__ v) {
    const int z = blockIdx.z;
    const float* B = w + (size_t)z * NW_ELEM;
    float*       C = (z == 0) ? q : (z == 1) ? k : v;

    float cf[4][4][4];
    gemm_main(x, B, cf);

    const int lane = threadIdx.x & 31;
    const int wid  = threadIdx.x >> 5;
    const int g    = lane >> 2;
    const int tg   = lane & 3;
    const int wm   = wid & 1;
    const int wn   = wid >> 1;
    const int bm   = blockIdx.y * 128;
    const int bn   = blockIdx.x * 128;

#pragma unroll
    for (int mt = 0; mt < 4; mt++) {
        int m0 = bm + wm * 64 + mt * 16 + g;
        float s_lo = (float)(m0 & (SEQ - 1));
        float s_hi = (float)((m0 + 8) & (SEQ - 1));
#pragma unroll
        for (int nt = 0; nt < 4; nt++) {
            int n0 = bn + wn * 32 + nt * 8 + 2 * tg;
            float2 lo = make_float2(cf[mt][nt][0], cf[mt][nt][1]);
            float2 hi = make_float2(cf[mt][nt][2], cf[mt][nt][3]);
            if (z < 2) {
                int d = (n0 & 63) >> 1;   // pair index within head, 0..31
                float inv = exp2f(-(float)d * (13.2877123795494935f / 32.0f));
                float sn_lo, cs_lo, sn_hi, cs_hi;
                sincosf(s_lo * inv, &sn_lo, &cs_lo);
                sincosf(s_hi * inv, &sn_hi, &cs_hi);
                float2 rlo = make_float2(lo.x * cs_lo - lo.y * sn_lo,
                                         lo.x * sn_lo + lo.y * cs_lo);
                float2 rhi = make_float2(hi.x * cs_hi - hi.y * sn_hi,
                                         hi.x * sn_hi + hi.y * cs_hi);
                if (z == 0) {
                    rlo.x *= 0.125f; rlo.y *= 0.125f;
                    rhi.x *= 0.125f; rhi.y *= 0.125f;
                }
                lo = rlo; hi = rhi;
            }
            *(float2*)&C[(size_t)m0 * D_MODEL + n0] =
                make_float2(f2tf_f(lo.x), f2tf_f(lo.y));
            *(float2*)&C[(size_t)(m0 + 8) * D_MODEL + n0] =
                make_float2(f2tf_f(hi.x), f2tf_f(hi.y));
        }
    }
}

// ---------------------------------------------------------------------------
// Flash attention v5: 128x64 tiles, 256 threads = 8 warps. Same pipeline as
// v4 (split K/V cp.async groups, double-buffered, P overlays Q slab), but all
// Q/K/P fragment pairs are LDS.64 via the 2tg slot convention.
// Pitches: Q/P = 72 (LDS.64 & STS.64 conflict-free: 8g+2tg), K = 72 (same),
// V = 68 (rows 2tg/2tg+1: banks 8tg+g / +4, conflict-free).
// ---------------------------------------------------------------------------
#define FQ 72
#define FK 72
#define FV 68
#define KSTG (64 * FK)      // 4608
#define VSTG (64 * FV)      // 4352
#define OQ  0               // Q/P slab: 128*72 = 9216
#define OKs 9216
#define OVs (OKs + 2 * KSTG)        // 18432
#define OM  (OVs + 2 * VSTG)        // 27136
#define FL5_SMEM ((OM + 128) * 4)   // 109056 B

__global__ __launch_bounds__(256, 2) void flash5(const float* __restrict__ q,
                                                 const float* __restrict__ k,
                                                 const float* __restrict__ v,
                                                 const int* __restrict__ mask,
                                                 float* __restrict__ ctx) {
    extern __shared__ float sm[];
    float* QPs = sm + OQ;
    int*   Msb = (int*)(sm + OM);

    const int T    = gridDim.x - 1 - blockIdx.x;   // heavy tiles first
    const int h    = blockIdx.y;
    const int b    = blockIdx.z;
    const int tid  = threadIdx.x;
    const int lane = tid & 31;
    const int wid  = tid >> 5;
    const int g    = lane >> 2;
    const int tg   = lane & 3;
    const int wrow = wid * 16;
    const size_t base = (size_t)b * SEQ;
    const uint32_t smb = (uint32_t)__cvta_generic_to_shared(sm);

    // Prologue. Group A: Q + K0 + mask0.  Group B: V0.
#pragma unroll
    for (int i = 0; i < 8; i++) {
        int c = i * 256 + tid;
        int row = c >> 4, col4 = (c & 15) * 4;
        cp16(smb + (OQ + row * FQ + col4) * 4,
             &q[(base + T * 128 + row) * D_MODEL + h * DK + col4]);
    }
#pragma unroll
    for (int i = 0; i < 4; i++) {
        int c = i * 256 + tid;
        int row = c >> 4, col4 = (c & 15) * 4;
        cp16(smb + (OKs + row * FK + col4) * 4,
             &k[(base + row) * D_MODEL + h * DK + col4]);
    }
    if (tid < 16) cp16(smb + OM * 4 + tid * 16, &mask[base + tid * 4]);
    cp_commit();
#pragma unroll
    for (int i = 0; i < 4; i++) {
        int c = i * 256 + tid;
        int row = c >> 4, col4 = (c & 15) * 4;
        cp16(smb + (OVs + row * FV + col4) * 4,
             &v[(base + row) * D_MODEL + h * DK + col4]);
    }
    cp_commit();

    float m_lo = -1e30f, m_hi = -1e30f, l_lo = 0.f, l_hi = 0.f;
    float of[8][4];
#pragma unroll
    for (int nt = 0; nt < 8; nt++)
#pragma unroll
        for (int j = 0; j < 4; j++) of[nt][j] = 0.f;

    unsigned qf[8][4];
    const int nkt = 2 * T + 2;

#pragma unroll 1
    for (int kt = 0; kt < nkt; kt++) {
        cp_wait<1>();       // K_kt (and Q) resident; V_kt may still fly
        __syncthreads();    // all warps done reading the other buffer

        const bool pf = (kt + 1 < nkt);
        if (pf) {           // prefetch tile kt+1: groups (K+mask), (V)
            int s = (kt + 1) & 1;
#pragma unroll
            for (int i = 0; i < 4; i++) {
                int c = i * 256 + tid;
                int row = c >> 4, col4 = (c & 15) * 4;
                cp16(smb + (OKs + s * KSTG + row * FK + col4) * 4,
                     &k[(base + (kt + 1) * 64 + row) * D_MODEL + h * DK + col4]);
            }
            if (tid < 16)
                cp16(smb + (OM + s * 64) * 4 + tid * 16,
                     &mask[base + (kt + 1) * 64 + tid * 4]);
            cp_commit();
#pragma unroll
            for (int i = 0; i < 4; i++) {
                int c = i * 256 + tid;
                int row = c >> 4, col4 = (c & 15) * 4;
                cp16(smb + (OVs + s * VSTG + row * FV + col4) * 4,
                     &v[(base + (kt + 1) * 64 + row) * D_MODEL + h * DK + col4]);
            }
            cp_commit();
        }

        const float* Ks = sm + OKs + (kt & 1) * KSTG;
        const float* Vs = sm + OVs + (kt & 1) * VSTG;
        const int*   Ms = Msb + (kt & 1) * 64;

        if (kt == 0) {   // hoist Q fragments (kt-invariant); before any P write
#pragma unroll
            for (int kc = 0; kc < 8; kc++) {
                float2 t0 = *(const float2*)&QPs[(wrow + g) * FQ + kc * 8 + 2 * tg];
                float2 t1 = *(const float2*)&QPs[(wrow + g + 8) * FQ + kc * 8 + 2 * tg];
                qf[kc][0] = __float_as_uint(t0.x);
                qf[kc][1] = __float_as_uint(t1.x);
                qf[kc][2] = __float_as_uint(t0.y);
                qf[kc][3] = __float_as_uint(t1.y);
            }
        }

        // ---- S = Q . K^T (V may still be in flight) ----
        float sf[8][4];
#pragma unroll
        for (int nt = 0; nt < 8; nt++) {
#pragma unroll
            for (int j = 0; j < 4; j++) sf[nt][j] = 0.f;
#pragma unroll
            for (int kc = 0; kc < 8; kc++) {
                float2 tk = *(const float2*)&Ks[(nt * 8 + g) * FK + kc * 8 + 2 * tg];
                mma8(sf[nt], qf[kc], __float_as_uint(tk.x), __float_as_uint(tk.y));
            }
        }

        // ---- padding mask ----
#pragma unroll
        for (int nt = 0; nt < 8; nt++) {
            if (Ms[nt * 8 + 2 * tg] == 0)     { sf[nt][0] = NEGV; sf[nt][2] = NEGV; }
            if (Ms[nt * 8 + 2 * tg + 1] == 0) { sf[nt][1] = NEGV; sf[nt][3] = NEGV; }
        }
        // ---- causal mask ----
        if (kt * 64 + 63 > T * 128 + wrow) {
            int r_lo = T * 128 + wrow + g;
            int r_hi = r_lo + 8;
#pragma unroll
            for (int nt = 0; nt < 8; nt++) {
                int c = kt * 64 + nt * 8 + 2 * tg;
                if (c > r_lo)     sf[nt][0] = NEGV;
                if (c + 1 > r_lo) sf[nt][1] = NEGV;
                if (c > r_hi)     sf[nt][2] = NEGV;
                if (c + 1 > r_hi) sf[nt][3] = NEGV;
            }
        }

        // ---- online softmax ----
        float mt_lo = sf[0][0], mt_hi = sf[0][2];
#pragma unroll
        for (int nt = 0; nt < 8; nt++) {
            mt_lo = fmaxf(mt_lo, fmaxf(sf[nt][0], sf[nt][1]));
            mt_hi = fmaxf(mt_hi, fmaxf(sf[nt][2], sf[nt][3]));
        }
        mt_lo = fmaxf(mt_lo, __shfl_xor_sync(0xffffffffu, mt_lo, 1));
        mt_lo = fmaxf(mt_lo, __shfl_xor_sync(0xffffffffu, mt_lo, 2));
        mt_hi = fmaxf(mt_hi, __shfl_xor_sync(0xffffffffu, mt_hi, 1));
        mt_hi = fmaxf(mt_hi, __shfl_xor_sync(0xffffffffu, mt_hi, 2));
        float mn_lo = fmaxf(m_lo, mt_lo);
        float mn_hi = fmaxf(m_hi, mt_hi);

        float lt_lo = 0.f, lt_hi = 0.f;
#pragma unroll
        for (int nt = 0; nt < 8; nt++) {
            sf[nt][0] = __expf(sf[nt][0] - mn_lo);
            sf[nt][1] = __expf(sf[nt][1] - mn_lo);
            sf[nt][2] = __expf(sf[nt][2] - mn_hi);
            sf[nt][3] = __expf(sf[nt][3] - mn_hi);
            lt_lo += sf[nt][0] + sf[nt][1];
            lt_hi += sf[nt][2] + sf[nt][3];
        }
        lt_lo += __shfl_xor_sync(0xffffffffu, lt_lo, 1);
        lt_lo += __shfl_xor_sync(0xffffffffu, lt_lo, 2);
        lt_hi += __shfl_xor_sync(0xffffffffu, lt_hi, 1);
        lt_hi += __shfl_xor_sync(0xffffffffu, lt_hi, 2);

        float a_lo = __expf(m_lo - mn_lo);
        float a_hi = __expf(m_hi - mn_hi);
        l_lo = l_lo * a_lo + lt_lo;
        l_hi = l_hi * a_hi + lt_hi;
        m_lo = mn_lo;
        m_hi = mn_hi;
#pragma unroll
        for (int nt = 0; nt < 8; nt++) {
            of[nt][0] *= a_lo;
            of[nt][1] *= a_lo;
            of[nt][2] *= a_hi;
            of[nt][3] *= a_hi;
        }

        // ---- P -> per-warp slab (overlaid on Q region) ----
#pragma unroll
        for (int nt = 0; nt < 8; nt++) {
            int pidx = (wrow + g) * FQ + nt * 8 + 2 * tg;
            *(float2*)&QPs[pidx] = make_float2(f2tf_f(sf[nt][0]), f2tf_f(sf[nt][1]));
            *(float2*)&QPs[pidx + 8 * FQ] = make_float2(f2tf_f(sf[nt][2]), f2tf_f(sf[nt][3]));
        }
        __syncwarp();

        // ---- wait for V_kt only now ----
        if (pf) cp_wait<2>();   // leave [K_{kt+1}, V_{kt+1}] in flight
        else    cp_wait<0>();

        // ---- O += P . V ----
        // A slot tg <- P col kc*8+2tg, slot tg+4 <- col kc*8+2tg+1 (LDS.64);
        // B slot tg <- V row kc*8+2tg, slot tg+4 <- row kc*8+2tg+1 (matches).
        unsigned af[8][4];
#pragma unroll
        for (int kc = 0; kc < 8; kc++) {
            float2 p0 = *(const float2*)&QPs[(wrow + g) * FQ + kc * 8 + 2 * tg];
            float2 p1 = *(const float2*)&QPs[(wrow + g + 8) * FQ + kc * 8 + 2 * tg];
            af[kc][0] = __float_as_uint(p0.x);
            af[kc][1] = __float_as_uint(p1.x);
            af[kc][2] = __float_as_uint(p0.y);
            af[kc][3] = __float_as_uint(p1.y);
        }
#pragma unroll
        for (int nt = 0; nt < 8; nt++) {
#pragma unroll
            for (int kc = 0; kc < 8; kc++) {
                unsigned bb0 = __float_as_uint(Vs[(kc * 8 + 2 * tg) * FV + nt * 8 + g]);
                unsigned bb1 = __float_as_uint(Vs[(kc * 8 + 2 * tg + 1) * FV + nt * 8 + g]);
                mma8(of[nt], af[kc], bb0, bb1);
            }
        }
        __syncwarp();   // P reads done before next tile overwrites
    }

    float inv_lo = 1.f / l_lo;
    float inv_hi = 1.f / l_hi;
    size_t row_lo = (base + T * 128 + wrow + g) * D_MODEL + h * DK;
    size_t row_hi = row_lo + 8 * D_MODEL;
#pragma unroll
    for (int nt = 0; nt < 8; nt++) {
        int n0 = nt * 8 + 2 * tg;
        *(float2*)&ctx[row_lo + n0] =
            make_float2(f2tf_f(of[nt][0] * inv_lo), f2tf_f(of[nt][1] * inv_lo));
        *(float2*)&ctx[row_hi + n0] =
            make_float2(f2tf_f(of[nt][2] * inv_hi), f2tf_f(of[nt][3] * inv_hi));
    }
}

// ---------------------------------------------------------------------------
extern "C" void kernel_launch(void* const* d_in, const int* in_sizes, int n_in,
                              void* d_out, int out_size) {
    const float* x  = (const float*)d_in[0];
    const int*   am = (const int*)d_in[1];
    const float* wq = (const float*)d_in[2];
    const float* wk = (const float*)d_in[3];
    const float* wv = (const float*)d_in[4];
    const float* wo = (const float*)d_in[5];

    float *q, *k, *v, *ctx, *xr, *wr;
    cudaGetSymbolAddress((void**)&q,   g_q);
    cudaGetSymbolAddress((void**)&k,   g_k);
    cudaGetSymbolAddress((void**)&v,   g_v);
    cudaGetSymbolAddress((void**)&ctx, g_ctx);
    cudaGetSymbolAddress((void**)&xr,  g_xr);
    cudaGetSymbolAddress((void**)&wr,  g_wr);

    cudaFuncSetAttribute(gemm_qkv, cudaFuncAttributeMaxDynamicSharedMemorySize, GEMM_SMEM);
    cudaFuncSetAttribute(gemm_out, cudaFuncAttributeMaxDynamicSharedMemorySize, GEMM_SMEM);
    cudaFuncSetAttribute(flash5,   cudaFuncAttributeMaxDynamicSharedMemorySize, FL5_SMEM);

    round_all<<<8192, 256>>>(x, wq, wk, wv, wo, xr, wr);

    dim3 gg(D_MODEL / 128, MTOK / 128, 3);
    gemm_qkv<<<gg, 256, GEMM_SMEM>>>(xr, wr, q, k, v);

    flash5<<<dim3(SEQ / 128, HEADS, BATCH), 256, FL5_SMEM>>>(q, k, v, am, ctx);

    dim3 go(D_MODEL / 128, MTOK / 128);
    gemm_out<<<go, 256, GEMM_SMEM>>>(ctx, wr + (size_t)3 * NW_ELEM, (float*)d_out);
}

// round 13
// speedup vs baseline: 1.0457x; 1.0457x over previous
#include <cuda_runtime.h>
#include <cstdint>

#define D_MODEL 1024
#define HEADS   16
#define DK      64
#define BATCH   2
#define SEQ     2048
#define MTOK    (BATCH * SEQ)   // 4096
#define NEGV    -1e9f

#define NW_ELEM (D_MODEL * D_MODEL)

// Scratch (allocation-free: static device globals)
__device__ float g_q[(size_t)MTOK * D_MODEL];
__device__ float g_k[(size_t)MTOK * D_MODEL];
__device__ float g_v[(size_t)MTOK * D_MODEL];
__device__ float g_ctx[(size_t)MTOK * D_MODEL];
__device__ float g_xr[(size_t)MTOK * D_MODEL];   // tf32-rounded x
__device__ float g_wr[(size_t)4 * NW_ELEM];      // tf32-rounded wq|wk|wv|wo

// ---------------------------------------------------------------------------
__device__ __forceinline__ unsigned f2tf(float x) {
    unsigned r;
    asm("cvt.rna.tf32.f32 %0, %1;" : "=r"(r) : "f"(x));
    return r;
}
__device__ __forceinline__ float f2tf_f(float x) { return __uint_as_float(f2tf(x)); }

__device__ __forceinline__ void mma8(float* c, const unsigned* a, unsigned b0, unsigned b1) {
    asm volatile(
        "mma.sync.aligned.m16n8k8.row.col.f32.tf32.tf32.f32 "
        "{%0,%1,%2,%3},{%4,%5,%6,%7},{%8,%9},{%0,%1,%2,%3};"
        : "+f"(c[0]), "+f"(c[1]), "+f"(c[2]), "+f"(c[3])
        : "r"(a[0]), "r"(a[1]), "r"(a[2]), "r"(a[3]), "r"(b0), "r"(b1));
}

__device__ __forceinline__ void cp16(uint32_t dst, const void* src) {
    asm volatile("cp.async.cg.shared.global [%0], [%1], 16;" :: "r"(dst), "l"(src));
}
__device__ __forceinline__ void cp_commit() {
    asm volatile("cp.async.commit_group;");
}
template <int N> __device__ __forceinline__ void cp_wait() {
    asm volatile("cp.async.wait_group %0;" :: "n"(N));
}

// ---------------------------------------------------------------------------
// Pre-round x and the four weights to tf32 (rna).
// ---------------------------------------------------------------------------
__global__ void round_all(const float* __restrict__ x,  const float* __restrict__ wq,
                          const float* __restrict__ wk, const float* __restrict__ wv,
                          const float* __restrict__ wo, float* __restrict__ xr,
                          float* __restrict__ wr) {
    const int NX = MTOK * D_MODEL / 4;
    const int NWq = NW_ELEM / 4;
    int i = blockIdx.x * blockDim.x + threadIdx.x;
    const float4* src;
    float4* dst;
    int off;
    if (i < NX) {
        src = (const float4*)x; dst = (float4*)xr; off = i;
    } else {
        int j = i - NX;
        int w = j >> 18;
        off = j & (NWq - 1);
        src = (const float4*)(w == 0 ? wq : w == 1 ? wk : w == 2 ? wv : wo);
        dst = (float4*)(wr + (size_t)w * NW_ELEM);
    }
    float4 t = src[off];
    dst[off] = make_float4(f2tf_f(t.x), f2tf_f(t.y), f2tf_f(t.z), f2tf_f(t.w));
}

// ---------------------------------------------------------------------------
// tf32 GEMM mainloop (NT): produces cf[4][4][4] per thread for a 128x128 tile.
// BK=32, cp.async double-buffered, 256 thr = 8 warps (2m x 4n).
// ---------------------------------------------------------------------------
#define BK    32
#define GROW  36
#define STAGE (128 * GROW)
#define GEMM_SMEM (4 * STAGE * 4)

__device__ __forceinline__ void gemm_main(const float* __restrict__ A,
                                          const float* __restrict__ B,
                                          float cf[4][4][4]) {
    extern __shared__ float sh[];
    float* As = sh;
    float* Bs = sh + 2 * STAGE;

    const int tid  = threadIdx.x;
    const int lane = tid & 31;
    const int wid  = tid >> 5;
    const int g    = lane >> 2;
    const int tg   = lane & 3;
    const int wm   = wid & 1;
    const int wn   = wid >> 1;
    const int bm   = blockIdx.y * 128;
    const int bn   = blockIdx.x * 128;

    const int r0 = tid >> 3;
    const int kc = tid & 7;
    const uint32_t sA = (uint32_t)__cvta_generic_to_shared(As) + (r0 * GROW + kc * 4) * 4;
    const uint32_t sB = (uint32_t)__cvta_generic_to_shared(Bs) + (r0 * GROW + kc * 4) * 4;
    const float* Ag = A + (size_t)(bm + r0) * D_MODEL + kc * 4;
    const float* Bg = B + (size_t)(bn + r0) * D_MODEL + kc * 4;

#pragma unroll
    for (int mt = 0; mt < 4; mt++)
#pragma unroll
        for (int nt = 0; nt < 4; nt++)
#pragma unroll
            for (int j = 0; j < 4; j++) cf[mt][nt][j] = 0.f;

    const int NIT = D_MODEL / BK;

#pragma unroll
    for (int i = 0; i < 4; i++) {
        cp16(sA + i * 32 * GROW * 4, Ag + (size_t)i * 32 * D_MODEL);
        cp16(sB + i * 32 * GROW * 4, Bg + (size_t)i * 32 * D_MODEL);
    }
    cp_commit();

#pragma unroll 1
    for (int it = 0; it < NIT; it++) {
        if (it + 1 < NIT) {
            int s = (it + 1) & 1;
            int k0 = (it + 1) * BK;
            uint32_t dA = sA + s * STAGE * 4;
            uint32_t dB = sB + s * STAGE * 4;
#pragma unroll
            for (int i = 0; i < 4; i++) {
                cp16(dA + i * 32 * GROW * 4, Ag + k0 + (size_t)i * 32 * D_MODEL);
                cp16(dB + i * 32 * GROW * 4, Bg + k0 + (size_t)i * 32 * D_MODEL);
            }
            cp_commit();
            cp_wait<1>();
        } else {
            cp_wait<0>();
        }
        __syncthreads();

        const float* as = As + (it & 1) * STAGE;
        const float* bs = Bs + (it & 1) * STAGE;
#pragma unroll
        for (int kb = 0; kb < BK; kb += 8) {
            unsigned af[4][4];
#pragma unroll
            for (int mt = 0; mt < 4; mt++) {
                int m = wm * 64 + mt * 16 + g;
                af[mt][0] = __float_as_uint(as[m * GROW + kb + tg]);
                af[mt][1] = __float_as_uint(as[(m + 8) * GROW + kb + tg]);
                af[mt][2] = __float_as_uint(as[m * GROW + kb + tg + 4]);
                af[mt][3] = __float_as_uint(as[(m + 8) * GROW + kb + tg + 4]);
            }
#pragma unroll
            for (int nt = 0; nt < 4; nt++) {
                int n = wn * 32 + nt * 8 + g;
                unsigned bb0 = __float_as_uint(bs[n * GROW + kb + tg]);
                unsigned bb1 = __float_as_uint(bs[n * GROW + kb + tg + 4]);
#pragma unroll
                for (int mt = 0; mt < 4; mt++) mma8(cf[mt][nt], af[mt], bb0, bb1);
            }
        }
        __syncthreads();
    }
}

// Plain output GEMM (final projection) — writes d_out directly.
__global__ __launch_bounds__(256, 2) void gemm_out(const float* __restrict__ A,
                                                   const float* __restrict__ B,
                                                   float* __restrict__ C) {
    float cf[4][4][4];
    gemm_main(A, B, cf);

    const int lane = threadIdx.x & 31;
    const int wid  = threadIdx.x >> 5;
    const int g    = lane >> 2;
    const int tg   = lane & 3;
    const int wm   = wid & 1;
    const int wn   = wid >> 1;
    const int bm   = blockIdx.y * 128;
    const int bn   = blockIdx.x * 128;

#pragma unroll
    for (int mt = 0; mt < 4; mt++) {
        int m0 = bm + wm * 64 + mt * 16 + g;
#pragma unroll
        for (int nt = 0; nt < 4; nt++) {
            int n0 = bn + wn * 32 + nt * 8 + 2 * tg;
            *(float2*)&C[(size_t)m0 * D_MODEL + n0] =
                make_float2(cf[mt][nt][0], cf[mt][nt][1]);
            *(float2*)&C[(size_t)(m0 + 8) * D_MODEL + n0] =
                make_float2(cf[mt][nt][2], cf[mt][nt][3]);
        }
    }
}

// QKV GEMM with fused RoPE + tf32 rounding epilogue.
// C-fragment holds column pairs (2tg, 2tg+1) = exactly the RoPE rotation pairs.
// z==0: rope + 0.125 scale (q); z==1: rope (k); z==2: round only (v).
__global__ __launch_bounds__(256, 2) void gemm_qkv(const float* __restrict__ x,
                                                   const float* __restrict__ w,
                                                   float* __restrict__ q,
                                                   float* __restrict__ k,
                                                   float* __restrict__ v) {
    const int z = blockIdx.z;
    const float* B = w + (size_t)z * NW_ELEM;
    float*       C = (z == 0) ? q : (z == 1) ? k : v;

    float cf[4][4][4];
    gemm_main(x, B, cf);

    const int lane = threadIdx.x & 31;
    const int wid  = threadIdx.x >> 5;
    const int g    = lane >> 2;
    const int tg   = lane & 3;
    const int wm   = wid & 1;
    const int wn   = wid >> 1;
    const int bm   = blockIdx.y * 128;
    const int bn   = blockIdx.x * 128;

#pragma unroll
    for (int mt = 0; mt < 4; mt++) {
        int m0 = bm + wm * 64 + mt * 16 + g;
        float s_lo = (float)(m0 & (SEQ - 1));
        float s_hi = (float)((m0 + 8) & (SEQ - 1));
#pragma unroll
        for (int nt = 0; nt < 4; nt++) {
            int n0 = bn + wn * 32 + nt * 8 + 2 * tg;
            float2 lo = make_float2(cf[mt][nt][0], cf[mt][nt][1]);
            float2 hi = make_float2(cf[mt][nt][2], cf[mt][nt][3]);
            if (z < 2) {
                int d = (n0 & 63) >> 1;   // pair index within head, 0..31
                float inv = exp2f(-(float)d * (13.2877123795494935f / 32.0f));
                float sn_lo, cs_lo, sn_hi, cs_hi;
                sincosf(s_lo * inv, &sn_lo, &cs_lo);
                sincosf(s_hi * inv, &sn_hi, &cs_hi);
                float2 rlo = make_float2(lo.x * cs_lo - lo.y * sn_lo,
                                         lo.x * sn_lo + lo.y * cs_lo);
                float2 rhi = make_float2(hi.x * cs_hi - hi.y * sn_hi,
                                         hi.x * sn_hi + hi.y * cs_hi);
                if (z == 0) {
                    rlo.x *= 0.125f; rlo.y *= 0.125f;
                    rhi.x *= 0.125f; rhi.y *= 0.125f;
                }
                lo = rlo; hi = rhi;
            }
            *(float2*)&C[(size_t)m0 * D_MODEL + n0] =
                make_float2(f2tf_f(lo.x), f2tf_f(lo.y));
            *(float2*)&C[(size_t)(m0 + 8) * D_MODEL + n0] =
                make_float2(f2tf_f(hi.x), f2tf_f(hi.y));
        }
    }
}

// ---------------------------------------------------------------------------
// Flash attention v4: 128x64 tiles, 256 threads = 8 warps. K and V in separate
// cp.async commit groups: S=QK^T starts as soon as K lands (V still in flight);
// PV waits for V only. K/V/mask double-buffered; prefetch overlaps compute.
// Ps overlays the Qs slab (Q fragments hoisted to registers at kt==0).
// ---------------------------------------------------------------------------
#define FQ 68
#define FV 72
#define KSTG (64 * FQ)
#define VSTG (64 * FV)
#define OQ  0
#define OKs 8704
#define OVs 17408
#define OM  26624
#define FL4_SMEM ((OM + 128) * 4)   // 107008 B

__global__ __launch_bounds__(256, 2) void flash4(const float* __restrict__ q,
                                                 const float* __restrict__ k,
                                                 const float* __restrict__ v,
                                                 const int* __restrict__ mask,
                                                 float* __restrict__ ctx) {
    extern __shared__ float sm[];
    float* QPs = sm + OQ;
    int*   Msb = (int*)(sm + OM);

    const int T    = gridDim.x - 1 - blockIdx.x;   // heavy tiles first
    const int h    = blockIdx.y;
    const int b    = blockIdx.z;
    const int tid  = threadIdx.x;
    const int lane = tid & 31;
    const int wid  = tid >> 5;
    const int g    = lane >> 2;
    const int tg   = lane & 3;
    const int wrow = wid * 16;
    const size_t base = (size_t)b * SEQ;
    const uint32_t smb = (uint32_t)__cvta_generic_to_shared(sm);

    // Prologue. Group A: Q + K0 + mask0.  Group B: V0.
#pragma unroll
    for (int i = 0; i < 8; i++) {
        int c = i * 256 + tid;
        int row = c >> 4, col4 = (c & 15) * 4;
        cp16(smb + (OQ + row * FQ + col4) * 4,
             &q[(base + T * 128 + row) * D_MODEL + h * DK + col4]);
    }
#pragma unroll
    for (int i = 0; i < 4; i++) {
        int c = i * 256 + tid;
        int row = c >> 4, col4 = (c & 15) * 4;
        cp16(smb + (OKs + row * FQ + col4) * 4,
             &k[(base + row) * D_MODEL + h * DK + col4]);
    }
    if (tid < 16) cp16(smb + OM * 4 + tid * 16, &mask[base + tid * 4]);
    cp_commit();
#pragma unroll
    for (int i = 0; i < 4; i++) {
        int c = i * 256 + tid;
        int row = c >> 4, col4 = (c & 15) * 4;
        cp16(smb + (OVs + row * FV + col4) * 4,
             &v[(base + row) * D_MODEL + h * DK + col4]);
    }
    cp_commit();

    float m_lo = -1e30f, m_hi = -1e30f, l_lo = 0.f, l_hi = 0.f;
    float of[8][4];
#pragma unroll
    for (int nt = 0; nt < 8; nt++)
#pragma unroll
        for (int j = 0; j < 4; j++) of[nt][j] = 0.f;

    unsigned qf[8][4];
    const int nkt = 2 * T + 2;

#pragma unroll 1
    for (int kt = 0; kt < nkt; kt++) {
        // Outstanding groups here: [K_kt(+Q,mask on kt==0), V_kt].
        cp_wait<1>();       // K_kt (and Q) resident; V_kt may still fly
        __syncthreads();    // all warps done reading the other buffer

        const bool pf = (kt + 1 < nkt);
        if (pf) {           // prefetch tile kt+1: groups C (K+mask), D (V)
            int s = (kt + 1) & 1;
#pragma unroll
            for (int i = 0; i < 4; i++) {
                int c = i * 256 + tid;
                int row = c >> 4, col4 = (c & 15) * 4;
                cp16(smb + (OKs + s * KSTG + row * FQ + col4) * 4,
                     &k[(base + (kt + 1) * 64 + row) * D_MODEL + h * DK + col4]);
            }
            if (tid < 16)
                cp16(smb + (OM + s * 64) * 4 + tid * 16,
                     &mask[base + (kt + 1) * 64 + tid * 4]);
            cp_commit();
#pragma unroll
            for (int i = 0; i < 4; i++) {
                int c = i * 256 + tid;
                int row = c >> 4, col4 = (c & 15) * 4;
                cp16(smb + (OVs + s * VSTG + row * FV + col4) * 4,
                     &v[(base + (kt + 1) * 64 + row) * D_MODEL + h * DK + col4]);
            }
            cp_commit();
        }

        const float* Ks = sm + OKs + (kt & 1) * KSTG;
        const float* Vs = sm + OVs + (kt & 1) * VSTG;
        const int*   Ms = Msb + (kt & 1) * 64;

        if (kt == 0) {   // hoist Q fragments (kt-invariant); before any Ps write
#pragma unroll
            for (int kc = 0; kc < 8; kc++) {
                qf[kc][0] = __float_as_uint(QPs[(wrow + g) * FQ + kc * 8 + tg]);
                qf[kc][1] = __float_as_uint(QPs[(wrow + g + 8) * FQ + kc * 8 + tg]);
                qf[kc][2] = __float_as_uint(QPs[(wrow + g) * FQ + kc * 8 + tg + 4]);
                qf[kc][3] = __float_as_uint(QPs[(wrow + g + 8) * FQ + kc * 8 + tg + 4]);
            }
        }

        // ---- S = Q . K^T (V may still be in flight) ----
        float sf[8][4];
#pragma unroll
        for (int nt = 0; nt < 8; nt++) {
#pragma unroll
            for (int j = 0; j < 4; j++) sf[nt][j] = 0.f;
#pragma unroll
            for (int kc = 0; kc < 8; kc++) {
                unsigned bb0 = __float_as_uint(Ks[(nt * 8 + g) * FQ + kc * 8 + tg]);
                unsigned bb1 = __float_as_uint(Ks[(nt * 8 + g) * FQ + kc * 8 + tg + 4]);
                mma8(sf[nt], qf[kc], bb0, bb1);
            }
        }

        // ---- padding mask ----
#pragma unroll
        for (int nt = 0; nt < 8; nt++) {
            if (Ms[nt * 8 + 2 * tg] == 0)     { sf[nt][0] = NEGV; sf[nt][2] = NEGV; }
            if (Ms[nt * 8 + 2 * tg + 1] == 0) { sf[nt][1] = NEGV; sf[nt][3] = NEGV; }
        }
        // ---- causal mask ----
        if (kt * 64 + 63 > T * 128 + wrow) {
            int r_lo = T * 128 + wrow + g;
            int r_hi = r_lo + 8;
#pragma unroll
            for (int nt = 0; nt < 8; nt++) {
                int c = kt * 64 + nt * 8 + 2 * tg;
                if (c > r_lo)     sf[nt][0] = NEGV;
                if (c + 1 > r_lo) sf[nt][1] = NEGV;
                if (c > r_hi)     sf[nt][2] = NEGV;
                if (c + 1 > r_hi) sf[nt][3] = NEGV;
            }
        }

        // ---- online softmax ----
        float mt_lo = sf[0][0], mt_hi = sf[0][2];
#pragma unroll
        for (int nt = 0; nt < 8; nt++) {
            mt_lo = fmaxf(mt_lo, fmaxf(sf[nt][0], sf[nt][1]));
            mt_hi = fmaxf(mt_hi, fmaxf(sf[nt][2], sf[nt][3]));
        }
        mt_lo = fmaxf(mt_lo, __shfl_xor_sync(0xffffffffu, mt_lo, 1));
        mt_lo = fmaxf(mt_lo, __shfl_xor_sync(0xffffffffu, mt_lo, 2));
        mt_hi = fmaxf(mt_hi, __shfl_xor_sync(0xffffffffu, mt_hi, 1));
        mt_hi = fmaxf(mt_hi, __shfl_xor_sync(0xffffffffu, mt_hi, 2));
        float mn_lo = fmaxf(m_lo, mt_lo);
        float mn_hi = fmaxf(m_hi, mt_hi);

        float lt_lo = 0.f, lt_hi = 0.f;
#pragma unroll
        for (int nt = 0; nt < 8; nt++) {
            sf[nt][0] = __expf(sf[nt][0] - mn_lo);
            sf[nt][1] = __expf(sf[nt][1] - mn_lo);
            sf[nt][2] = __expf(sf[nt][2] - mn_hi);
            sf[nt][3] = __expf(sf[nt][3] - mn_hi);
            lt_lo += sf[nt][0] + sf[nt][1];
            lt_hi += sf[nt][2] + sf[nt][3];
        }
        lt_lo += __shfl_xor_sync(0xffffffffu, lt_lo, 1);
        lt_lo += __shfl_xor_sync(0xffffffffu, lt_lo, 2);
        lt_hi += __shfl_xor_sync(0xffffffffu, lt_hi, 1);
        lt_hi += __shfl_xor_sync(0xffffffffu, lt_hi, 2);

        float a_lo = __expf(m_lo - mn_lo);
        float a_hi = __expf(m_hi - mn_hi);
        l_lo = l_lo * a_lo + lt_lo;
        l_hi = l_hi * a_hi + lt_hi;
        m_lo = mn_lo;
        m_hi = mn_hi;
#pragma unroll
        for (int nt = 0; nt < 8; nt++) {
            of[nt][0] *= a_lo;
            of[nt][1] *= a_lo;
            of[nt][2] *= a_hi;
            of[nt][3] *= a_hi;
        }

        // ---- P -> per-warp slab (overlaid on Q region) ----
#pragma unroll
        for (int nt = 0; nt < 8; nt++) {
            int pidx = (wrow + g) * FQ + nt * 8 + 2 * tg;
            *(float2*)&QPs[pidx] = make_float2(f2tf_f(sf[nt][0]), f2tf_f(sf[nt][1]));
            *(float2*)&QPs[pidx + 8 * FQ] = make_float2(f2tf_f(sf[nt][2]), f2tf_f(sf[nt][3]));
        }
        __syncwarp();

        // ---- wait for V_kt only now ----
        if (pf) cp_wait<2>();   // leave [K_{kt+1}, V_{kt+1}] in flight
        else    cp_wait<0>();

        // ---- O += P . V ----
        unsigned af[8][4];
#pragma unroll
        for (int kc = 0; kc < 8; kc++) {
            af[kc][0] = __float_as_uint(QPs[(wrow + g) * FQ + kc * 8 + tg]);
            af[kc][1] = __float_as_uint(QPs[(wrow + g + 8) * FQ + kc * 8 + tg]);
            af[kc][2] = __float_as_uint(QPs[(wrow + g) * FQ + kc * 8 + tg + 4]);
            af[kc][3] = __float_as_uint(QPs[(wrow + g + 8) * FQ + kc * 8 + tg + 4]);
        }
#pragma unroll
        for (int nt = 0; nt < 8; nt++) {
#pragma unroll
            for (int kc = 0; kc < 8; kc++) {
                unsigned bb0 = __float_as_uint(Vs[(kc * 8 + tg) * FV + nt * 8 + g]);
                unsigned bb1 = __float_as_uint(Vs[(kc * 8 + tg + 4) * FV + nt * 8 + g]);
                mma8(of[nt], af[kc], bb0, bb1);
            }
        }
        __syncwarp();   // P reads done before next tile overwrites
    }

    float inv_lo = 1.f / l_lo;
    float inv_hi = 1.f / l_hi;
    size_t row_lo = (base + T * 128 + wrow + g) * D_MODEL + h * DK;
    size_t row_hi = row_lo + 8 * D_MODEL;
#pragma unroll
    for (int nt = 0; nt < 8; nt++) {
        int n0 = nt * 8 + 2 * tg;
        *(float2*)&ctx[row_lo + n0] =
            make_float2(f2tf_f(of[nt][0] * inv_lo), f2tf_f(of[nt][1] * inv_lo));
        *(float2*)&ctx[row_hi + n0] =
            make_float2(f2tf_f(of[nt][2] * inv_hi), f2tf_f(of[nt][3] * inv_hi));
    }
}

// ---------------------------------------------------------------------------
extern "C" void kernel_launch(void* const* d_in, const int* in_sizes, int n_in,
                              void* d_out, int out_size) {
    const float* x  = (const float*)d_in[0];
    const int*   am = (const int*)d_in[1];
    const float* wq = (const float*)d_in[2];
    const float* wk = (const float*)d_in[3];
    const float* wv = (const float*)d_in[4];
    const float* wo = (const float*)d_in[5];

    float *q, *k, *v, *ctx, *xr, *wr;
    cudaGetSymbolAddress((void**)&q,   g_q);
    cudaGetSymbolAddress((void**)&k,   g_k);
    cudaGetSymbolAddress((void**)&v,   g_v);
    cudaGetSymbolAddress((void**)&ctx, g_ctx);
    cudaGetSymbolAddress((void**)&xr,  g_xr);
    cudaGetSymbolAddress((void**)&wr,  g_wr);

    cudaFuncSetAttribute(gemm_qkv, cudaFuncAttributeMaxDynamicSharedMemorySize, GEMM_SMEM);
    cudaFuncSetAttribute(gemm_out, cudaFuncAttributeMaxDynamicSharedMemorySize, GEMM_SMEM);
    cudaFuncSetAttribute(flash4,   cudaFuncAttributeMaxDynamicSharedMemorySize, FL4_SMEM);

    round_all<<<8192, 256>>>(x, wq, wk, wv, wo, xr, wr);

    dim3 gg(D_MODEL / 128, MTOK / 128, 3);
    gemm_qkv<<<gg, 256, GEMM_SMEM>>>(xr, wr, q, k, v);

    flash4<<<dim3(SEQ / 128, HEADS, BATCH), 256, FL4_SMEM>>>(q, k, v, am, ctx);

    dim3 go(D_MODEL / 128, MTOK / 128);
    gemm_out<<<go, 256, GEMM_SMEM>>>(ctx, wr + (size_t)3 * NW_ELEM, (float*)d_out);
}

// round 15
// speedup vs baseline: 1.1413x; 1.0915x over previous
#include <cuda_runtime.h>
#include <cstdint>

#define D_MODEL 1024
#define HEADS   16
#define DK      64
#define BATCH   2
#define SEQ     2048
#define MTOK    (BATCH * SEQ)   // 4096
#define NEGV    -1e9f

#define NW_ELEM (D_MODEL * D_MODEL)

// Scratch (allocation-free: static device globals)
__device__ float g_q[(size_t)MTOK * D_MODEL];
__device__ float g_k[(size_t)MTOK * D_MODEL];
__device__ float g_v[(size_t)MTOK * D_MODEL];
__device__ float g_ctx[(size_t)MTOK * D_MODEL];
__device__ float g_xr[(size_t)MTOK * D_MODEL];   // tf32-rounded x
__device__ float g_wr[(size_t)4 * NW_ELEM];      // tf32-rounded wq|wk|wv|wo

// ---------------------------------------------------------------------------
__device__ __forceinline__ unsigned f2tf(float x) {
    unsigned r;
    asm("cvt.rna.tf32.f32 %0, %1;" : "=r"(r) : "f"(x));
    return r;
}
__device__ __forceinline__ float f2tf_f(float x) { return __uint_as_float(f2tf(x)); }

__device__ __forceinline__ void mma8(float* c, const unsigned* a, unsigned b0, unsigned b1) {
    asm volatile(
        "mma.sync.aligned.m16n8k8.row.col.f32.tf32.tf32.f32 "
        "{%0,%1,%2,%3},{%4,%5,%6,%7},{%8,%9},{%0,%1,%2,%3};"
        : "+f"(c[0]), "+f"(c[1]), "+f"(c[2]), "+f"(c[3])
        : "r"(a[0]), "r"(a[1]), "r"(a[2]), "r"(a[3]), "r"(b0), "r"(b1));
}

__device__ __forceinline__ void cp16(uint32_t dst, const void* src) {
    asm volatile("cp.async.cg.shared.global [%0], [%1], 16;" :: "r"(dst), "l"(src));
}
__device__ __forceinline__ void cp_commit() {
    asm volatile("cp.async.commit_group;");
}
template <int N> __device__ __forceinline__ void cp_wait() {
    asm volatile("cp.async.wait_group %0;" :: "n"(N));
}

// ---------------------------------------------------------------------------
// Pre-round x and the four weights to tf32 (rna).
// ---------------------------------------------------------------------------
__global__ void round_all(const float* __restrict__ x,  const float* __restrict__ wq,
                          const float* __restrict__ wk, const float* __restrict__ wv,
                          const float* __restrict__ wo, float* __restrict__ xr,
                          float* __restrict__ wr) {
    const int NX = MTOK * D_MODEL / 4;
    const int NWq = NW_ELEM / 4;
    int i = blockIdx.x * blockDim.x + threadIdx.x;
    const float4* src;
    float4* dst;
    int off;
    if (i < NX) {
        src = (const float4*)x; dst = (float4*)xr; off = i;
    } else {
        int j = i - NX;
        int w = j >> 18;
        off = j & (NWq - 1);
        src = (const float4*)(w == 0 ? wq : w == 1 ? wk : w == 2 ? wv : wo);
        dst = (float4*)(wr + (size_t)w * NW_ELEM);
    }
    float4 t = src[off];
    dst[off] = make_float4(f2tf_f(t.x), f2tf_f(t.y), f2tf_f(t.z), f2tf_f(t.w));
}

// ---------------------------------------------------------------------------
// tf32 GEMM mainloop (NT): produces cf[4][4][4] per thread for a 128x128 tile.
// BK=32, cp.async double-buffered, 256 thr = 8 warps (2m x 4n).
// ---------------------------------------------------------------------------
#define BK    32
#define GROW  36
#define STAGE (128 * GROW)
#define GEMM_SMEM (4 * STAGE * 4)

__device__ __forceinline__ void gemm_main(const float* __restrict__ A,
                                          const float* __restrict__ B,
                                          float cf[4][4][4]) {
    extern __shared__ float sh[];
    float* As = sh;
    float* Bs = sh + 2 * STAGE;

    const int tid  = threadIdx.x;
    const int lane = tid & 31;
    const int wid  = tid >> 5;
    const int g    = lane >> 2;
    const int tg   = lane & 3;
    const int wm   = wid & 1;
    const int wn   = wid >> 1;
    const int bm   = blockIdx.y * 128;
    const int bn   = blockIdx.x * 128;

    const int r0 = tid >> 3;
    const int kc = tid & 7;
    const uint32_t sA = (uint32_t)__cvta_generic_to_shared(As) + (r0 * GROW + kc * 4) * 4;
    const uint32_t sB = (uint32_t)__cvta_generic_to_shared(Bs) + (r0 * GROW + kc * 4) * 4;
    const float* Ag = A + (size_t)(bm + r0) * D_MODEL + kc * 4;
    const float* Bg = B + (size_t)(bn + r0) * D_MODEL + kc * 4;

#pragma unroll
    for (int mt = 0; mt < 4; mt++)
#pragma unroll
        for (int nt = 0; nt < 4; nt++)
#pragma unroll
            for (int j = 0; j < 4; j++) cf[mt][nt][j] = 0.f;

    const int NIT = D_MODEL / BK;

#pragma unroll
    for (int i = 0; i < 4; i++) {
        cp16(sA + i * 32 * GROW * 4, Ag + (size_t)i * 32 * D_MODEL);
        cp16(sB + i * 32 * GROW * 4, Bg + (size_t)i * 32 * D_MODEL);
    }
    cp_commit();

#pragma unroll 1
    for (int it = 0; it < NIT; it++) {
        if (it + 1 < NIT) {
            int s = (it + 1) & 1;
            int k0 = (it + 1) * BK;
            uint32_t dA = sA + s * STAGE * 4;
            uint32_t dB = sB + s * STAGE * 4;
#pragma unroll
            for (int i = 0; i < 4; i++) {
                cp16(dA + i * 32 * GROW * 4, Ag + k0 + (size_t)i * 32 * D_MODEL);
                cp16(dB + i * 32 * GROW * 4, Bg + k0 + (size_t)i * 32 * D_MODEL);
            }
            cp_commit();
            cp_wait<1>();
        } else {
            cp_wait<0>();
        }
        __syncthreads();

        const float* as = As + (it & 1) * STAGE;
        const float* bs = Bs + (it & 1) * STAGE;
#pragma unroll
        for (int kb = 0; kb < BK; kb += 8) {
            unsigned af[4][4];
#pragma unroll
            for (int mt = 0; mt < 4; mt++) {
                int m = wm * 64 + mt * 16 + g;
                af[mt][0] = __float_as_uint(as[m * GROW + kb + tg]);
                af[mt][1] = __float_as_uint(as[(m + 8) * GROW + kb + tg]);
                af[mt][2] = __float_as_uint(as[m * GROW + kb + tg + 4]);
                af[mt][3] = __float_as_uint(as[(m + 8) * GROW + kb + tg + 4]);
            }
#pragma unroll
            for (int nt = 0; nt < 4; nt++) {
                int n = wn * 32 + nt * 8 + g;
                unsigned bb0 = __float_as_uint(bs[n * GROW + kb + tg]);
                unsigned bb1 = __float_as_uint(bs[n * GROW + kb + tg + 4]);
#pragma unroll
                for (int mt = 0; mt < 4; mt++) mma8(cf[mt][nt], af[mt], bb0, bb1);
            }
        }
        __syncthreads();
    }
}

// Plain output GEMM (final projection) — writes d_out directly.
__global__ __launch_bounds__(256, 2) void gemm_out(const float* __restrict__ A,
                                                   const float* __restrict__ B,
                                                   float* __restrict__ C) {
    float cf[4][4][4];
    gemm_main(A, B, cf);

    const int lane = threadIdx.x & 31;
    const int wid  = threadIdx.x >> 5;
    const int g    = lane >> 2;
    const int tg   = lane & 3;
    const int wm   = wid & 1;
    const int wn   = wid >> 1;
    const int bm   = blockIdx.y * 128;
    const int bn   = blockIdx.x * 128;

#pragma unroll
    for (int mt = 0; mt < 4; mt++) {
        int m0 = bm + wm * 64 + mt * 16 + g;
#pragma unroll
        for (int nt = 0; nt < 4; nt++) {
            int n0 = bn + wn * 32 + nt * 8 + 2 * tg;
            *(float2*)&C[(size_t)m0 * D_MODEL + n0] =
                make_float2(cf[mt][nt][0], cf[mt][nt][1]);
            *(float2*)&C[(size_t)(m0 + 8) * D_MODEL + n0] =
                make_float2(cf[mt][nt][2], cf[mt][nt][3]);
        }
    }
}

// QKV GEMM with fused RoPE + tf32 rounding epilogue.
// C-fragment holds column pairs (2tg, 2tg+1) = exactly the RoPE rotation pairs.
// z==0: rope + 0.125 scale (q); z==1: rope (k); z==2: round only (v).
__global__ __launch_bounds__(256, 2) void gemm_qkv(const float* __restrict__ x,
                                                   const float* __restrict__ w,
                                                   float* __restrict__ q,
                                                   float* __restrict__ k,
                                                   float* __restrict__ v) {
    const int z = blockIdx.z;
    const float* B = w + (size_t)z * NW_ELEM;
    float*       C = (z == 0) ? q : (z == 1) ? k : v;

    float cf[4][4][4];
    gemm_main(x, B, cf);

    const int lane = threadIdx.x & 31;
    const int wid  = threadIdx.x >> 5;
    const int g    = lane >> 2;
    const int tg   = lane & 3;
    const int wm   = wid & 1;
    const int wn   = wid >> 1;
    const int bm   = blockIdx.y * 128;
    const int bn   = blockIdx.x * 128;

#pragma unroll
    for (int mt = 0; mt < 4; mt++) {
        int m0 = bm + wm * 64 + mt * 16 + g;
        float s_lo = (float)(m0 & (SEQ - 1));
        float s_hi = (float)((m0 + 8) & (SEQ - 1));
#pragma unroll
        for (int nt = 0; nt < 4; nt++) {
            int n0 = bn + wn * 32 + nt * 8 + 2 * tg;
            float2 lo = make_float2(cf[mt][nt][0], cf[mt][nt][1]);
            float2 hi = make_float2(cf[mt][nt][2], cf[mt][nt][3]);
            if (z < 2) {
                int d = (n0 & 63) >> 1;   // pair index within head, 0..31
                float inv = exp2f(-(float)d * (13.2877123795494935f / 32.0f));
                float sn_lo, cs_lo, sn_hi, cs_hi;
                sincosf(s_lo * inv, &sn_lo, &cs_lo);
                sincosf(s_hi * inv, &sn_hi, &cs_hi);
                float2 rlo = make_float2(lo.x * cs_lo - lo.y * sn_lo,
                                         lo.x * sn_lo + lo.y * cs_lo);
                float2 rhi = make_float2(hi.x * cs_hi - hi.y * sn_hi,
                                         hi.x * sn_hi + hi.y * cs_hi);
                if (z == 0) {
                    rlo.x *= 0.125f; rlo.y *= 0.125f;
                    rhi.x *= 0.125f; rhi.y *= 0.125f;
                }
                lo = rlo; hi = rhi;
            }
            *(float2*)&C[(size_t)m0 * D_MODEL + n0] =
                make_float2(f2tf_f(lo.x), f2tf_f(lo.y));
            *(float2*)&C[(size_t)(m0 + 8) * D_MODEL + n0] =
                make_float2(f2tf_f(hi.x), f2tf_f(hi.y));
        }
    }
}

// ---------------------------------------------------------------------------
// Flash attention v6: 128x64 tiles, 256 threads = 8 warps. Same per-tile
// pipeline as v4 (split K/V cp.async groups, double-buffered, P overlays Q),
// but each CTA processes a BALANCED PAIR of q-tiles: T = 8+bx (heavy) then
// T = 7-bx (light). Every CTA does exactly 34 k-tiles -> one uniform wave
// (256 CTAs <= 296 resident slots), no wave-2 tail.
// ---------------------------------------------------------------------------
#define FQ 68
#define FV 72
#define KSTG (64 * FQ)
#define VSTG (64 * FV)
#define OQ  0
#define OKs 8704
#define OVs 17408
#define OM  26624
#define FL6_SMEM ((OM + 128) * 4)   // 107008 B

__global__ __launch_bounds__(256, 2) void flash6(const float* __restrict__ q,
                                                 const float* __restrict__ k,
                                                 const float* __restrict__ v,
                                                 const int* __restrict__ mask,
                                                 float* __restrict__ ctx) {
    extern __shared__ float sm[];
    float* QPs = sm + OQ;
    int*   Msb = (int*)(sm + OM);

    const int bx   = blockIdx.x;           // 0..7
    const int h    = blockIdx.y;
    const int b    = blockIdx.z;
    const int tid  = threadIdx.x;
    const int lane = tid & 31;
    const int wid  = tid >> 5;
    const int g    = lane >> 2;
    const int tg   = lane & 3;
    const int wrow = wid * 16;
    const size_t base = (size_t)b * SEQ;
    const uint32_t smb = (uint32_t)__cvta_generic_to_shared(sm);

#pragma unroll 1
    for (int ph = 0; ph < 2; ph++) {
        const int T = (ph == 0) ? (8 + bx) : (7 - bx);   // heavy tile first

        // Prologue. Group A: Q + K0 + mask0.  Group B: V0.
#pragma unroll
        for (int i = 0; i < 8; i++) {
            int c = i * 256 + tid;
            int row = c >> 4, col4 = (c & 15) * 4;
            cp16(smb + (OQ + row * FQ + col4) * 4,
                 &q[(base + T * 128 + row) * D_MODEL + h * DK + col4]);
        }
#pragma unroll
        for (int i = 0; i < 4; i++) {
            int c = i * 256 + tid;
            int row = c >> 4, col4 = (c & 15) * 4;
            cp16(smb + (OKs + row * FQ + col4) * 4,
                 &k[(base + row) * D_MODEL + h * DK + col4]);
        }
        if (tid < 16) cp16(smb + OM * 4 + tid * 16, &mask[base + tid * 4]);
        cp_commit();
#pragma unroll
        for (int i = 0; i < 4; i++) {
            int c = i * 256 + tid;
            int row = c >> 4, col4 = (c & 15) * 4;
            cp16(smb + (OVs + row * FV + col4) * 4,
                 &v[(base + row) * D_MODEL + h * DK + col4]);
        }
        cp_commit();

        float m_lo = -1e30f, m_hi = -1e30f, l_lo = 0.f, l_hi = 0.f;
        float of[8][4];
#pragma unroll
        for (int nt = 0; nt < 8; nt++)
#pragma unroll
            for (int j = 0; j < 4; j++) of[nt][j] = 0.f;

        unsigned qf[8][4];
        const int nkt = 2 * T + 2;

#pragma unroll 1
        for (int kt = 0; kt < nkt; kt++) {
            // Outstanding groups here: [K_kt(+Q,mask on kt==0), V_kt].
            cp_wait<1>();       // K_kt (and Q) resident; V_kt may still fly
            __syncthreads();    // all warps done reading the other buffer

            const bool pf = (kt + 1 < nkt);
            if (pf) {           // prefetch tile kt+1: groups (K+mask), (V)
                int s = (kt + 1) & 1;
#pragma unroll
                for (int i = 0; i < 4; i++) {
                    int c = i * 256 + tid;
                    int row = c >> 4, col4 = (c & 15) * 4;
                    cp16(smb + (OKs + s * KSTG + row * FQ + col4) * 4,
                         &k[(base + (kt + 1) * 64 + row) * D_MODEL + h * DK + col4]);
                }
                if (tid < 16)
                    cp16(smb + (OM + s * 64) * 4 + tid * 16,
                         &mask[base + (kt + 1) * 64 + tid * 4]);
                cp_commit();
#pragma unroll
                for (int i = 0; i < 4; i++) {
                    int c = i * 256 + tid;
                    int row = c >> 4, col4 = (c & 15) * 4;
                    cp16(smb + (OVs + s * VSTG + row * FV + col4) * 4,
                         &v[(base + (kt + 1) * 64 + row) * D_MODEL + h * DK + col4]);
                }
                cp_commit();
            }

            const float* Ks = sm + OKs + (kt & 1) * KSTG;
            const float* Vs = sm + OVs + (kt & 1) * VSTG;
            const int*   Ms = Msb + (kt & 1) * 64;

            if (kt == 0) {   // hoist Q fragments (kt-invariant); before any P write
#pragma unroll
                for (int kc = 0; kc < 8; kc++) {
                    qf[kc][0] = __float_as_uint(QPs[(wrow + g) * FQ + kc * 8 + tg]);
                    qf[kc][1] = __float_as_uint(QPs[(wrow + g + 8) * FQ + kc * 8 + tg]);
                    qf[kc][2] = __float_as_uint(QPs[(wrow + g) * FQ + kc * 8 + tg + 4]);
                    qf[kc][3] = __float_as_uint(QPs[(wrow + g + 8) * FQ + kc * 8 + tg + 4]);
                }
            }

            // ---- S = Q . K^T (V may still be in flight) ----
            float sf[8][4];
#pragma unroll
            for (int nt = 0; nt < 8; nt++) {
#pragma unroll
                for (int j = 0; j < 4; j++) sf[nt][j] = 0.f;
#pragma unroll
                for (int kc = 0; kc < 8; kc++) {
                    unsigned bb0 = __float_as_uint(Ks[(nt * 8 + g) * FQ + kc * 8 + tg]);
                    unsigned bb1 = __float_as_uint(Ks[(nt * 8 + g) * FQ + kc * 8 + tg + 4]);
                    mma8(sf[nt], qf[kc], bb0, bb1);
                }
            }

            // ---- padding mask ----
#pragma unroll
            for (int nt = 0; nt < 8; nt++) {
                if (Ms[nt * 8 + 2 * tg] == 0)     { sf[nt][0] = NEGV; sf[nt][2] = NEGV; }
                if (Ms[nt * 8 + 2 * tg + 1] == 0) { sf[nt][1] = NEGV; sf[nt][3] = NEGV; }
            }
            // ---- causal mask ----
            if (kt * 64 + 63 > T * 128 + wrow) {
                int r_lo = T * 128 + wrow + g;
                int r_hi = r_lo + 8;
#pragma unroll
                for (int nt = 0; nt < 8; nt++) {
                    int c = kt * 64 + nt * 8 + 2 * tg;
                    if (c > r_lo)     sf[nt][0] = NEGV;
                    if (c + 1 > r_lo) sf[nt][1] = NEGV;
                    if (c > r_hi)     sf[nt][2] = NEGV;
                    if (c + 1 > r_hi) sf[nt][3] = NEGV;
                }
            }

            // ---- online softmax ----
            float mt_lo = sf[0][0], mt_hi = sf[0][2];
#pragma unroll
            for (int nt = 0; nt < 8; nt++) {
                mt_lo = fmaxf(mt_lo, fmaxf(sf[nt][0], sf[nt][1]));
                mt_hi = fmaxf(mt_hi, fmaxf(sf[nt][2], sf[nt][3]));
            }
            mt_lo = fmaxf(mt_lo, __shfl_xor_sync(0xffffffffu, mt_lo, 1));
            mt_lo = fmaxf(mt_lo, __shfl_xor_sync(0xffffffffu, mt_lo, 2));
            mt_hi = fmaxf(mt_hi, __shfl_xor_sync(0xffffffffu, mt_hi, 1));
            mt_hi = fmaxf(mt_hi, __shfl_xor_sync(0xffffffffu, mt_hi, 2));
            float mn_lo = fmaxf(m_lo, mt_lo);
            float mn_hi = fmaxf(m_hi, mt_hi);

            float lt_lo = 0.f, lt_hi = 0.f;
#pragma unroll
            for (int nt = 0; nt < 8; nt++) {
                sf[nt][0] = __expf(sf[nt][0] - mn_lo);
                sf[nt][1] = __expf(sf[nt][1] - mn_lo);
                sf[nt][2] = __expf(sf[nt][2] - mn_hi);
                sf[nt][3] = __expf(sf[nt][3] - mn_hi);
                lt_lo += sf[nt][0] + sf[nt][1];
                lt_hi += sf[nt][2] + sf[nt][3];
            }
            lt_lo += __shfl_xor_sync(0xffffffffu, lt_lo, 1);
            lt_lo += __shfl_xor_sync(0xffffffffu, lt_lo, 2);
            lt_hi += __shfl_xor_sync(0xffffffffu, lt_hi, 1);
            lt_hi += __shfl_xor_sync(0xffffffffu, lt_hi, 2);

            float a_lo = __expf(m_lo - mn_lo);
            float a_hi = __expf(m_hi - mn_hi);
            l_lo = l_lo * a_lo + lt_lo;
            l_hi = l_hi * a_hi + lt_hi;
            m_lo = mn_lo;
            m_hi = mn_hi;
#pragma unroll
            for (int nt = 0; nt < 8; nt++) {
                of[nt][0] *= a_lo;
                of[nt][1] *= a_lo;
                of[nt][2] *= a_hi;
                of[nt][3] *= a_hi;
            }

            // ---- P -> per-warp slab (overlaid on Q region) ----
#pragma unroll
            for (int nt = 0; nt < 8; nt++) {
                int pidx = (wrow + g) * FQ + nt * 8 + 2 * tg;
                *(float2*)&QPs[pidx] = make_float2(f2tf_f(sf[nt][0]), f2tf_f(sf[nt][1]));
                *(float2*)&QPs[pidx + 8 * FQ] = make_float2(f2tf_f(sf[nt][2]), f2tf_f(sf[nt][3]));
            }
            __syncwarp();

            // ---- wait for V_kt only now ----
            if (pf) cp_wait<2>();   // leave [K_{kt+1}, V_{kt+1}] in flight
            else    cp_wait<0>();

            // ---- O += P . V ----
            unsigned af[8][4];
#pragma unroll
            for (int kc = 0; kc < 8; kc++) {
                af[kc][0] = __float_as_uint(QPs[(wrow + g) * FQ + kc * 8 + tg]);
                af[kc][1] = __float_as_uint(QPs[(wrow + g + 8) * FQ + kc * 8 + tg]);
                af[kc][2] = __float_as_uint(QPs[(wrow + g) * FQ + kc * 8 + tg + 4]);
                af[kc][3] = __float_as_uint(QPs[(wrow + g + 8) * FQ + kc * 8 + tg + 4]);
            }
#pragma unroll
            for (int nt = 0; nt < 8; nt++) {
#pragma unroll
                for (int kc = 0; kc < 8; kc++) {
                    unsigned bb0 = __float_as_uint(Vs[(kc * 8 + tg) * FV + nt * 8 + g]);
                    unsigned bb1 = __float_as_uint(Vs[(kc * 8 + tg + 4) * FV + nt * 8 + g]);
                    mma8(of[nt], af[kc], bb0, bb1);
                }
            }
            __syncwarp();   // P reads done before next tile overwrites
        }

        float inv_lo = 1.f / l_lo;
        float inv_hi = 1.f / l_hi;
        size_t row_lo = (base + T * 128 + wrow + g) * D_MODEL + h * DK;
        size_t row_hi = row_lo + 8 * D_MODEL;
#pragma unroll
        for (int nt = 0; nt < 8; nt++) {
            int n0 = nt * 8 + 2 * tg;
            *(float2*)&ctx[row_lo + n0] =
                make_float2(f2tf_f(of[nt][0] * inv_lo), f2tf_f(of[nt][1] * inv_lo));
            *(float2*)&ctx[row_hi + n0] =
                make_float2(f2tf_f(of[nt][2] * inv_hi), f2tf_f(of[nt][3] * inv_hi));
        }

        __syncthreads();   // smem (QPs/Ks/Vs/Ms) safe to reuse for next phase
    }
}

// ---------------------------------------------------------------------------
extern "C" void kernel_launch(void* const* d_in, const int* in_sizes, int n_in,
                              void* d_out, int out_size) {
    const float* x  = (const float*)d_in[0];
    const int*   am = (const int*)d_in[1];
    const float* wq = (const float*)d_in[2];
    const float* wk = (const float*)d_in[3];
    const float* wv = (const float*)d_in[4];
    const float* wo = (const float*)d_in[5];

    float *q, *k, *v, *ctx, *xr, *wr;
    cudaGetSymbolAddress((void**)&q,   g_q);
    cudaGetSymbolAddress((void**)&k,   g_k);
    cudaGetSymbolAddress((void**)&v,   g_v);
    cudaGetSymbolAddress((void**)&ctx, g_ctx);
    cudaGetSymbolAddress((void**)&xr,  g_xr);
    cudaGetSymbolAddress((void**)&wr,  g_wr);

    cudaFuncSetAttribute(gemm_qkv, cudaFuncAttributeMaxDynamicSharedMemorySize, GEMM_SMEM);
    cudaFuncSetAttribute(gemm_out, cudaFuncAttributeMaxDynamicSharedMemorySize, GEMM_SMEM);
    cudaFuncSetAttribute(flash6,   cudaFuncAttributeMaxDynamicSharedMemorySize, FL6_SMEM);

    round_all<<<8192, 256>>>(x, wq, wk, wv, wo, xr, wr);

    dim3 gg(D_MODEL / 128, MTOK / 128, 3);
    gemm_qkv<<<gg, 256, GEMM_SMEM>>>(xr, wr, q, k, v);

    flash6<<<dim3(SEQ / 256, HEADS, BATCH), 256, FL6_SMEM>>>(q, k, v, am, ctx);

    dim3 go(D_MODEL / 128, MTOK / 128);
    gemm_out<<<go, 256, GEMM_SMEM>>>(ctx, wr + (size_t)3 * NW_ELEM, (float*)d_out);
}

// round 16
// speedup vs baseline: 1.1522x; 1.0096x over previous
#include <cuda_runtime.h>
#include <cstdint>

#define D_MODEL 1024
#define HEADS   16
#define DK      64
#define BATCH   2
#define SEQ     2048
#define MTOK    (BATCH * SEQ)   // 4096
#define NEGV    -1e9f
// q pre-scale: (1/sqrt(DK)) * log2(e) -> scores in base-2 space, softmax uses exp2f
#define QSCALE  0.18033688011112042f

#define NW_ELEM (D_MODEL * D_MODEL)

// Scratch (allocation-free: static device globals)
__device__ float g_q[(size_t)MTOK * D_MODEL];
__device__ float g_k[(size_t)MTOK * D_MODEL];
__device__ float g_v[(size_t)MTOK * D_MODEL];
__device__ float g_ctx[(size_t)MTOK * D_MODEL];
__device__ float g_xr[(size_t)MTOK * D_MODEL];   // tf32-rounded x
__device__ float g_wr[(size_t)4 * NW_ELEM];      // tf32-rounded wq|wk|wv|wo

// ---------------------------------------------------------------------------
__device__ __forceinline__ unsigned f2tf(float x) {
    unsigned r;
    asm("cvt.rna.tf32.f32 %0, %1;" : "=r"(r) : "f"(x));
    return r;
}
__device__ __forceinline__ float f2tf_f(float x) { return __uint_as_float(f2tf(x)); }

__device__ __forceinline__ void mma8(float* c, const unsigned* a, unsigned b0, unsigned b1) {
    asm volatile(
        "mma.sync.aligned.m16n8k8.row.col.f32.tf32.tf32.f32 "
        "{%0,%1,%2,%3},{%4,%5,%6,%7},{%8,%9},{%0,%1,%2,%3};"
        : "+f"(c[0]), "+f"(c[1]), "+f"(c[2]), "+f"(c[3])
        : "r"(a[0]), "r"(a[1]), "r"(a[2]), "r"(a[3]), "r"(b0), "r"(b1));
}

__device__ __forceinline__ void cp16(uint32_t dst, const void* src) {
    asm volatile("cp.async.cg.shared.global [%0], [%1], 16;" :: "r"(dst), "l"(src));
}
__device__ __forceinline__ void cp_commit() {
    asm volatile("cp.async.commit_group;");
}
template <int N> __device__ __forceinline__ void cp_wait() {
    asm volatile("cp.async.wait_group %0;" :: "n"(N));
}

// ---------------------------------------------------------------------------
// Pre-round x and the four weights to tf32 (rna).
// ---------------------------------------------------------------------------
__global__ void round_all(const float* __restrict__ x,  const float* __restrict__ wq,
                          const float* __restrict__ wk, const float* __restrict__ wv,
                          const float* __restrict__ wo, float* __restrict__ xr,
                          float* __restrict__ wr) {
    const int NX = MTOK * D_MODEL / 4;
    const int NWq = NW_ELEM / 4;
    int i = blockIdx.x * blockDim.x + threadIdx.x;
    const float4* src;
    float4* dst;
    int off;
    if (i < NX) {
        src = (const float4*)x; dst = (float4*)xr; off = i;
    } else {
        int j = i - NX;
        int w = j >> 18;
        off = j & (NWq - 1);
        src = (const float4*)(w == 0 ? wq : w == 1 ? wk : w == 2 ? wv : wo);
        dst = (float4*)(wr + (size_t)w * NW_ELEM);
    }
    float4 t = src[off];
    dst[off] = make_float4(f2tf_f(t.x), f2tf_f(t.y), f2tf_f(t.z), f2tf_f(t.w));
}

// ---------------------------------------------------------------------------
// tf32 GEMM mainloop (NT): produces cf[4][4][4] per thread for a 128x128 tile.
// BK=32, cp.async double-buffered, 256 thr = 8 warps (2m x 4n).
// ---------------------------------------------------------------------------
#define BK    32
#define GROW  36
#define STAGE (128 * GROW)
#define GEMM_SMEM (4 * STAGE * 4)

__device__ __forceinline__ void gemm_main(const float* __restrict__ A,
                                          const float* __restrict__ B,
                                          float cf[4][4][4]) {
    extern __shared__ float sh[];
    float* As = sh;
    float* Bs = sh + 2 * STAGE;

    const int tid  = threadIdx.x;
    const int lane = tid & 31;
    const int wid  = tid >> 5;
    const int g    = lane >> 2;
    const int tg   = lane & 3;
    const int wm   = wid & 1;
    const int wn   = wid >> 1;
    const int bm   = blockIdx.y * 128;
    const int bn   = blockIdx.x * 128;

    const int r0 = tid >> 3;
    const int kc = tid & 7;
    const uint32_t sA = (uint32_t)__cvta_generic_to_shared(As) + (r0 * GROW + kc * 4) * 4;
    const uint32_t sB = (uint32_t)__cvta_generic_to_shared(Bs) + (r0 * GROW + kc * 4) * 4;
    const float* Ag = A + (size_t)(bm + r0) * D_MODEL + kc * 4;
    const float* Bg = B + (size_t)(bn + r0) * D_MODEL + kc * 4;

#pragma unroll
    for (int mt = 0; mt < 4; mt++)
#pragma unroll
        for (int nt = 0; nt < 4; nt++)
#pragma unroll
            for (int j = 0; j < 4; j++) cf[mt][nt][j] = 0.f;

    const int NIT = D_MODEL / BK;

#pragma unroll
    for (int i = 0; i < 4; i++) {
        cp16(sA + i * 32 * GROW * 4, Ag + (size_t)i * 32 * D_MODEL);
        cp16(sB + i * 32 * GROW * 4, Bg + (size_t)i * 32 * D_MODEL);
    }
    cp_commit();

#pragma unroll 1
    for (int it = 0; it < NIT; it++) {
        if (it + 1 < NIT) {
            int s = (it + 1) & 1;
            int k0 = (it + 1) * BK;
            uint32_t dA = sA + s * STAGE * 4;
            uint32_t dB = sB + s * STAGE * 4;
#pragma unroll
            for (int i = 0; i < 4; i++) {
                cp16(dA + i * 32 * GROW * 4, Ag + k0 + (size_t)i * 32 * D_MODEL);
                cp16(dB + i * 32 * GROW * 4, Bg + k0 + (size_t)i * 32 * D_MODEL);
            }
            cp_commit();
            cp_wait<1>();
        } else {
            cp_wait<0>();
        }
        __syncthreads();

        const float* as = As + (it & 1) * STAGE;
        const float* bs = Bs + (it & 1) * STAGE;
#pragma unroll
        for (int kb = 0; kb < BK; kb += 8) {
            unsigned af[4][4];
#pragma unroll
            for (int mt = 0; mt < 4; mt++) {
                int m = wm * 64 + mt * 16 + g;
                af[mt][0] = __float_as_uint(as[m * GROW + kb + tg]);
                af[mt][1] = __float_as_uint(as[(m + 8) * GROW + kb + tg]);
                af[mt][2] = __float_as_uint(as[m * GROW + kb + tg + 4]);
                af[mt][3] = __float_as_uint(as[(m + 8) * GROW + kb + tg + 4]);
            }
#pragma unroll
            for (int nt = 0; nt < 4; nt++) {
                int n = wn * 32 + nt * 8 + g;
                unsigned bb0 = __float_as_uint(bs[n * GROW + kb + tg]);
                unsigned bb1 = __float_as_uint(bs[n * GROW + kb + tg + 4]);
#pragma unroll
                for (int mt = 0; mt < 4; mt++) mma8(cf[mt][nt], af[mt], bb0, bb1);
            }
        }
        __syncthreads();
    }
}

// Plain output GEMM (final projection) — writes d_out directly.
__global__ __launch_bounds__(256, 2) void gemm_out(const float* __restrict__ A,
                                                   const float* __restrict__ B,
                                                   float* __restrict__ C) {
    float cf[4][4][4];
    gemm_main(A, B, cf);

    const int lane = threadIdx.x & 31;
    const int wid  = threadIdx.x >> 5;
    const int g    = lane >> 2;
    const int tg   = lane & 3;
    const int wm   = wid & 1;
    const int wn   = wid >> 1;
    const int bm   = blockIdx.y * 128;
    const int bn   = blockIdx.x * 128;

#pragma unroll
    for (int mt = 0; mt < 4; mt++) {
        int m0 = bm + wm * 64 + mt * 16 + g;
#pragma unroll
        for (int nt = 0; nt < 4; nt++) {
            int n0 = bn + wn * 32 + nt * 8 + 2 * tg;
            *(float2*)&C[(size_t)m0 * D_MODEL + n0] =
                make_float2(cf[mt][nt][0], cf[mt][nt][1]);
            *(float2*)&C[(size_t)(m0 + 8) * D_MODEL + n0] =
                make_float2(cf[mt][nt][2], cf[mt][nt][3]);
        }
    }
}

// QKV GEMM with fused RoPE + tf32 rounding epilogue.
// z==0: rope + QSCALE (q, log2-space scores); z==1: rope (k); z==2: round (v).
__global__ __launch_bounds__(256, 2) void gemm_qkv(const float* __restrict__ x,
                                                   const float* __restrict__ w,
                                                   float* __restrict__ q,
                                                   float* __restrict__ k,
                                                   float* __restrict__ v) {
    const int z = blockIdx.z;
    const float* B = w + (size_t)z * NW_ELEM;
    float*       C = (z == 0) ? q : (z == 1) ? k : v;

    float cf[4][4][4];
    gemm_main(x, B, cf);

    const int lane = threadIdx.x & 31;
    const int wid  = threadIdx.x >> 5;
    const int g    = lane >> 2;
    const int tg   = lane & 3;
    const int wm   = wid & 1;
    const int wn   = wid >> 1;
    const int bm   = blockIdx.y * 128;
    const int bn   = blockIdx.x * 128;

#pragma unroll
    for (int mt = 0; mt < 4; mt++) {
        int m0 = bm + wm * 64 + mt * 16 + g;
        float s_lo = (float)(m0 & (SEQ - 1));
        float s_hi = (float)((m0 + 8) & (SEQ - 1));
#pragma unroll
        for (int nt = 0; nt < 4; nt++) {
            int n0 = bn + wn * 32 + nt * 8 + 2 * tg;
            float2 lo = make_float2(cf[mt][nt][0], cf[mt][nt][1]);
            float2 hi = make_float2(cf[mt][nt][2], cf[mt][nt][3]);
            if (z < 2) {
                int d = (n0 & 63) >> 1;   // pair index within head, 0..31
                float inv = exp2f(-(float)d * (13.2877123795494935f / 32.0f));
                float sn_lo, cs_lo, sn_hi, cs_hi;
                sincosf(s_lo * inv, &sn_lo, &cs_lo);
                sincosf(s_hi * inv, &sn_hi, &cs_hi);
                float2 rlo = make_float2(lo.x * cs_lo - lo.y * sn_lo,
                                         lo.x * sn_lo + lo.y * cs_lo);
                float2 rhi = make_float2(hi.x * cs_hi - hi.y * sn_hi,
                                         hi.x * sn_hi + hi.y * cs_hi);
                if (z == 0) {
                    rlo.x *= QSCALE; rlo.y *= QSCALE;
                    rhi.x *= QSCALE; rhi.y *= QSCALE;
                }
                lo = rlo; hi = rhi;
            }
            *(float2*)&C[(size_t)m0 * D_MODEL + n0] =
                make_float2(f2tf_f(lo.x), f2tf_f(lo.y));
            *(float2*)&C[(size_t)(m0 + 8) * D_MODEL + n0] =
                make_float2(f2tf_f(hi.x), f2tf_f(hi.y));
        }
    }
}

// ---------------------------------------------------------------------------
// Flash attention v7: balanced-pair scheduling (flash6) + log2-space softmax:
// scores arrive pre-scaled by log2(e)/8, so p = exp2f(s - m) is a single
// MUFU.EX2 (no FMUL) -> ~34 fewer issued instrs per thread per tile.
// ---------------------------------------------------------------------------
#define FQ 68
#define FV 72
#define KSTG (64 * FQ)
#define VSTG (64 * FV)
#define OQ  0
#define OKs 8704
#define OVs 17408
#define OM  26624
#define FL7_SMEM ((OM + 128) * 4)   // 107008 B

__global__ __launch_bounds__(256, 2) void flash7(const float* __restrict__ q,
                                                 const float* __restrict__ k,
                                                 const float* __restrict__ v,
                                                 const int* __restrict__ mask,
                                                 float* __restrict__ ctx) {
    extern __shared__ float sm[];
    float* QPs = sm + OQ;
    int*   Msb = (int*)(sm + OM);

    const int bx   = blockIdx.x;           // 0..7
    const int h    = blockIdx.y;
    const int b    = blockIdx.z;
    const int tid  = threadIdx.x;
    const int lane = tid & 31;
    const int wid  = tid >> 5;
    const int g    = lane >> 2;
    const int tg   = lane & 3;
    const int wrow = wid * 16;
    const size_t base = (size_t)b * SEQ;
    const uint32_t smb = (uint32_t)__cvta_generic_to_shared(sm);

#pragma unroll 1
    for (int ph = 0; ph < 2; ph++) {
        const int T = (ph == 0) ? (8 + bx) : (7 - bx);   // heavy tile first

        // Prologue. Group A: Q + K0 + mask0.  Group B: V0.
#pragma unroll
        for (int i = 0; i < 8; i++) {
            int c = i * 256 + tid;
            int row = c >> 4, col4 = (c & 15) * 4;
            cp16(smb + (OQ + row * FQ + col4) * 4,
                 &q[(base + T * 128 + row) * D_MODEL + h * DK + col4]);
        }
#pragma unroll
        for (int i = 0; i < 4; i++) {
            int c = i * 256 + tid;
            int row = c >> 4, col4 = (c & 15) * 4;
            cp16(smb + (OKs + row * FQ + col4) * 4,
                 &k[(base + row) * D_MODEL + h * DK + col4]);
        }
        if (tid < 16) cp16(smb + OM * 4 + tid * 16, &mask[base + tid * 4]);
        cp_commit();
#pragma unroll
        for (int i = 0; i < 4; i++) {
            int c = i * 256 + tid;
            int row = c >> 4, col4 = (c & 15) * 4;
            cp16(smb + (OVs + row * FV + col4) * 4,
                 &v[(base + row) * D_MODEL + h * DK + col4]);
        }
        cp_commit();

        float m_lo = -1e30f, m_hi = -1e30f, l_lo = 0.f, l_hi = 0.f;
        float of[8][4];
#pragma unroll
        for (int nt = 0; nt < 8; nt++)
#pragma unroll
            for (int j = 0; j < 4; j++) of[nt][j] = 0.f;

        unsigned qf[8][4];
        const int nkt = 2 * T + 2;

#pragma unroll 1
        for (int kt = 0; kt < nkt; kt++) {
            // Outstanding groups here: [K_kt(+Q,mask on kt==0), V_kt].
            cp_wait<1>();       // K_kt (and Q) resident; V_kt may still fly
            __syncthreads();    // all warps done reading the other buffer

            const bool pf = (kt + 1 < nkt);
            if (pf) {           // prefetch tile kt+1: groups (K+mask), (V)
                int s = (kt + 1) & 1;
#pragma unroll
                for (int i = 0; i < 4; i++) {
                    int c = i * 256 + tid;
                    int row = c >> 4, col4 = (c & 15) * 4;
                    cp16(smb + (OKs + s * KSTG + row * FQ + col4) * 4,
                         &k[(base + (kt + 1) * 64 + row) * D_MODEL + h * DK + col4]);
                }
                if (tid < 16)
                    cp16(smb + (OM + s * 64) * 4 + tid * 16,
                         &mask[base + (kt + 1) * 64 + tid * 4]);
                cp_commit();
#pragma unroll
                for (int i = 0; i < 4; i++) {
                    int c = i * 256 + tid;
                    int row = c >> 4, col4 = (c & 15) * 4;
                    cp16(smb + (OVs + s * VSTG + row * FV + col4) * 4,
                         &v[(base + (kt + 1) * 64 + row) * D_MODEL + h * DK + col4]);
                }
                cp_commit();
            }

            const float* Ks = sm + OKs + (kt & 1) * KSTG;
            const float* Vs = sm + OVs + (kt & 1) * VSTG;
            const int*   Ms = Msb + (kt & 1) * 64;

            if (kt == 0) {   // hoist Q fragments (kt-invariant); before any P write
#pragma unroll
                for (int kc = 0; kc < 8; kc++) {
                    qf[kc][0] = __float_as_uint(QPs[(wrow + g) * FQ + kc * 8 + tg]);
                    qf[kc][1] = __float_as_uint(QPs[(wrow + g + 8) * FQ + kc * 8 + tg]);
                    qf[kc][2] = __float_as_uint(QPs[(wrow + g) * FQ + kc * 8 + tg + 4]);
                    qf[kc][3] = __float_as_uint(QPs[(wrow + g + 8) * FQ + kc * 8 + tg + 4]);
                }
            }

            // ---- S = Q . K^T (base-2 scaled; V may still be in flight) ----
            float sf[8][4];
#pragma unroll
            for (int nt = 0; nt < 8; nt++) {
#pragma unroll
                for (int j = 0; j < 4; j++) sf[nt][j] = 0.f;
#pragma unroll
                for (int kc = 0; kc < 8; kc++) {
                    unsigned bb0 = __float_as_uint(Ks[(nt * 8 + g) * FQ + kc * 8 + tg]);
                    unsigned bb1 = __float_as_uint(Ks[(nt * 8 + g) * FQ + kc * 8 + tg + 4]);
                    mma8(sf[nt], qf[kc], bb0, bb1);
                }
            }

            // ---- padding mask ----
#pragma unroll
            for (int nt = 0; nt < 8; nt++) {
                if (Ms[nt * 8 + 2 * tg] == 0)     { sf[nt][0] = NEGV; sf[nt][2] = NEGV; }
                if (Ms[nt * 8 + 2 * tg + 1] == 0) { sf[nt][1] = NEGV; sf[nt][3] = NEGV; }
            }
            // ---- causal mask ----
            if (kt * 64 + 63 > T * 128 + wrow) {
                int r_lo = T * 128 + wrow + g;
                int r_hi = r_lo + 8;
#pragma unroll
                for (int nt = 0; nt < 8; nt++) {
                    int c = kt * 64 + nt * 8 + 2 * tg;
                    if (c > r_lo)     sf[nt][0] = NEGV;
                    if (c + 1 > r_lo) sf[nt][1] = NEGV;
                    if (c > r_hi)     sf[nt][2] = NEGV;
                    if (c + 1 > r_hi) sf[nt][3] = NEGV;
                }
            }

            // ---- online softmax (base 2: p = 2^(s - m)) ----
            float mt_lo = sf[0][0], mt_hi = sf[0][2];
#pragma unroll
            for (int nt = 0; nt < 8; nt++) {
                mt_lo = fmaxf(mt_lo, fmaxf(sf[nt][0], sf[nt][1]));
                mt_hi = fmaxf(mt_hi, fmaxf(sf[nt][2], sf[nt][3]));
            }
            mt_lo = fmaxf(mt_lo, __shfl_xor_sync(0xffffffffu, mt_lo, 1));
            mt_lo = fmaxf(mt_lo, __shfl_xor_sync(0xffffffffu, mt_lo, 2));
            mt_hi = fmaxf(mt_hi, __shfl_xor_sync(0xffffffffu, mt_hi, 1));
            mt_hi = fmaxf(mt_hi, __shfl_xor_sync(0xffffffffu, mt_hi, 2));
            float mn_lo = fmaxf(m_lo, mt_lo);
            float mn_hi = fmaxf(m_hi, mt_hi);

            float lt_lo = 0.f, lt_hi = 0.f;
#pragma unroll
            for (int nt = 0; nt < 8; nt++) {
                sf[nt][0] = exp2f(sf[nt][0] - mn_lo);
                sf[nt][1] = exp2f(sf[nt][1] - mn_lo);
                sf[nt][2] = exp2f(sf[nt][2] - mn_hi);
                sf[nt][3] = exp2f(sf[nt][3] - mn_hi);
                lt_lo += sf[nt][0] + sf[nt][1];
                lt_hi += sf[nt][2] + sf[nt][3];
            }
            lt_lo += __shfl_xor_sync(0xffffffffu, lt_lo, 1);
            lt_lo += __shfl_xor_sync(0xffffffffu, lt_lo, 2);
            lt_hi += __shfl_xor_sync(0xffffffffu, lt_hi, 1);
            lt_hi += __shfl_xor_sync(0xffffffffu, lt_hi, 2);

            float a_lo = exp2f(m_lo - mn_lo);
            float a_hi = exp2f(m_hi - mn_hi);
            l_lo = l_lo * a_lo + lt_lo;
            l_hi = l_hi * a_hi + lt_hi;
            m_lo = mn_lo;
            m_hi = mn_hi;
#pragma unroll
            for (int nt = 0; nt < 8; nt++) {
                of[nt][0] *= a_lo;
                of[nt][1] *= a_lo;
                of[nt][2] *= a_hi;
                of[nt][3] *= a_hi;
            }

            // ---- P -> per-warp slab (overlaid on Q region) ----
#pragma unroll
            for (int nt = 0; nt < 8; nt++) {
                int pidx = (wrow + g) * FQ + nt * 8 + 2 * tg;
                *(float2*)&QPs[pidx] = make_float2(f2tf_f(sf[nt][0]), f2tf_f(sf[nt][1]));
                *(float2*)&QPs[pidx + 8 * FQ] = make_float2(f2tf_f(sf[nt][2]), f2tf_f(sf[nt][3]));
            }
            __syncwarp();

            // ---- wait for V_kt only now ----
            if (pf) cp_wait<2>();   // leave [K_{kt+1}, V_{kt+1}] in flight
            else    cp_wait<0>();

            // ---- O += P . V ----
            unsigned af[8][4];
#pragma unroll
            for (int kc = 0; kc < 8; kc++) {
                af[kc][0] = __float_as_uint(QPs[(wrow + g) * FQ + kc * 8 + tg]);
                af[kc][1] = __float_as_uint(QPs[(wrow + g + 8) * FQ + kc * 8 + tg]);
                af[kc][2] = __float_as_uint(QPs[(wrow + g) * FQ + kc * 8 + tg + 4]);
                af[kc][3] = __float_as_uint(QPs[(wrow + g + 8) * FQ + kc * 8 + tg + 4]);
            }
#pragma unroll
            for (int nt = 0; nt < 8; nt++) {
#pragma unroll
                for (int kc = 0; kc < 8; kc++) {
                    unsigned bb0 = __float_as_uint(Vs[(kc * 8 + tg) * FV + nt * 8 + g]);
                    unsigned bb1 = __float_as_uint(Vs[(kc * 8 + tg + 4) * FV + nt * 8 + g]);
                    mma8(of[nt], af[kc], bb0, bb1);
                }
            }
            __syncwarp();   // P reads done before next tile overwrites
        }

        float inv_lo = 1.f / l_lo;
        float inv_hi = 1.f / l_hi;
        size_t row_lo = (base + T * 128 + wrow + g) * D_MODEL + h * DK;
        size_t row_hi = row_lo + 8 * D_MODEL;
#pragma unroll
        for (int nt = 0; nt < 8; nt++) {
            int n0 = nt * 8 + 2 * tg;
            *(float2*)&ctx[row_lo + n0] =
                make_float2(f2tf_f(of[nt][0] * inv_lo), f2tf_f(of[nt][1] * inv_lo));
            *(float2*)&ctx[row_hi + n0] =
                make_float2(f2tf_f(of[nt][2] * inv_hi), f2tf_f(of[nt][3] * inv_hi));
        }

        __syncthreads();   // smem (QPs/Ks/Vs/Ms) safe to reuse for next phase
    }
}

// ---------------------------------------------------------------------------
extern "C" void kernel_launch(void* const* d_in, const int* in_sizes, int n_in,
                              void* d_out, int out_size) {
    const float* x  = (const float*)d_in[0];
    const int*   am = (const int*)d_in[1];
    const float* wq = (const float*)d_in[2];
    const float* wk = (const float*)d_in[3];
    const float* wv = (const float*)d_in[4];
    const float* wo = (const float*)d_in[5];

    float *q, *k, *v, *ctx, *xr, *wr;
    cudaGetSymbolAddress((void**)&q,   g_q);
    cudaGetSymbolAddress((void**)&k,   g_k);
    cudaGetSymbolAddress((void**)&v,   g_v);
    cudaGetSymbolAddress((void**)&ctx, g_ctx);
    cudaGetSymbolAddress((void**)&xr,  g_xr);
    cudaGetSymbolAddress((void**)&wr,  g_wr);

    cudaFuncSetAttribute(gemm_qkv, cudaFuncAttributeMaxDynamicSharedMemorySize, GEMM_SMEM);
    cudaFuncSetAttribute(gemm_out, cudaFuncAttributeMaxDynamicSharedMemorySize, GEMM_SMEM);
    cudaFuncSetAttribute(flash7,   cudaFuncAttributeMaxDynamicSharedMemorySize, FL7_SMEM);

    round_all<<<8192, 256>>>(x, wq, wk, wv, wo, xr, wr);

    dim3 gg(D_MODEL / 128, MTOK / 128, 3);
    gemm_qkv<<<gg, 256, GEMM_SMEM>>>(xr, wr, q, k, v);

    flash7<<<dim3(SEQ / 256, HEADS, BATCH), 256, FL7_SMEM>>>(q, k, v, am, ctx);

    dim3 go(D_MODEL / 128, MTOK / 128);
    gemm_out<<<go, 256, GEMM_SMEM>>>(ctx, wr + (size_t)3 * NW_ELEM, (float*)d_out);
}